// round 11
// baseline (speedup 1.0000x reference)
#include <cuda_runtime.h>
#include <cstdint>

#define NN 100000
#define EE 1600000
#define SCAN_BLK 2048          // elements per scan block (256 threads x 8)
#define MAX_PARTS 128

typedef unsigned long long u64;

// f32x2 packed helpers (sm_100+): bit-exact 2-wide fp32 FMA, 2x FFMA throughput
__device__ __forceinline__ u64 pk2(float x) {
    u64 r; asm("mov.b64 %0, {%1, %1};" : "=l"(r) : "f"(x)); return r;
}
__device__ __forceinline__ void fma2(u64& d, u64 a, u64 b) {
    asm("fma.rn.f32x2 %0, %1, %2, %0;" : "+l"(d) : "l"(a), "l"(b));
}
__device__ __forceinline__ void unpk2(u64 v, float& lo, float& hi) {
    asm("mov.b64 {%0, %1}, %2;" : "=f"(lo), "=f"(hi) : "l"(v));
}

// ---------------- scratch (device globals; no allocations allowed) -------------
__device__ int   g_cnt[NN];            // in-degree (edges only)
__device__ int   g_rowptr[NN + 1];     // CSR row pointers (by dst)
__device__ int   g_cursor[NN];         // fill cursors
__device__ int   g_csrc[EE];           // CSR src indices
__device__ int   g_part[MAX_PARTS];    // scan partials
__device__ float g_dinv[NN];
__device__ float g_T[NN * 64];         // Ts = (h @ W) * dinv[row]
__device__ float g_H[4 * NN * 64];     // per-layer post-relu features
__device__ float g_M[64 * 64];         // Wq @ Wk^T
__device__ float g_scores[4 * NN];

// ---------------- degree / CSR build --------------------------------------------
__global__ void k_zerocnt(int n) {
    int i = blockIdx.x * 256 + threadIdx.x;
    if (i < n) g_cnt[i] = 0;
}

__global__ void k_count(const int* __restrict__ ei, int E) {
    int e = blockIdx.x * 256 + threadIdx.x;
    if (e < E) atomicAdd(&g_cnt[ei[E + e]], 1);
}

// ---- scan phase 1: per-block reduce + dinv  -------------------------------------
__global__ void __launch_bounds__(256) k_scan1(int n) {
    int tid = threadIdx.x;
    int base = blockIdx.x * SCAN_BLK + tid * 8;
    int s = 0;
#pragma unroll
    for (int k = 0; k < 8; k++) {
        int i = base + k;
        if (i < n) {
            int c = g_cnt[i];
            s += c;
            g_dinv[i] = rsqrtf((float)(c + 1));   // +1 self loop
        }
    }
#pragma unroll
    for (int off = 16; off; off >>= 1) s += __shfl_xor_sync(0xffffffffu, s, off);
    __shared__ int sw[8];
    if ((tid & 31) == 0) sw[tid >> 5] = s;
    __syncthreads();
    if (tid == 0) {
        int t = 0;
#pragma unroll
        for (int w = 0; w < 8; w++) t += sw[w];
        g_part[blockIdx.x] = t;
    }
}

// ---- scan phase 2: exclusive scan of partials (single small block) --------------
__global__ void k_scan2(int nparts, int n) {
    __shared__ int sh[MAX_PARTS];
    int tid = threadIdx.x;
    sh[tid] = (tid < nparts) ? g_part[tid] : 0;
    __syncthreads();
    for (int off = 1; off < MAX_PARTS; off <<= 1) {
        int t = (tid >= off) ? sh[tid - off] : 0;
        __syncthreads();
        sh[tid] += t;
        __syncthreads();
    }
    if (tid < nparts) g_part[tid] = (tid ? sh[tid - 1] : 0);
    if (tid == MAX_PARTS - 1) g_rowptr[n] = sh[MAX_PARTS - 1];
}

// ---- scan phase 3: block-local exclusive scan + offset -> rowptr/cursor ---------
__global__ void __launch_bounds__(256) k_scan3(int n) {
    __shared__ int sw[8];
    int tid = threadIdx.x;
    int base = blockIdx.x * SCAN_BLK + tid * 8;
    int v[8];
    int s = 0;
#pragma unroll
    for (int k = 0; k < 8; k++) {
        int i = base + k;
        int c = (i < n) ? g_cnt[i] : 0;
        v[k] = s;          // exclusive within thread
        s += c;
    }
    int lane = tid & 31, w = tid >> 5;
    int incl = s;
#pragma unroll
    for (int off = 1; off < 32; off <<= 1) {
        int t = __shfl_up_sync(0xffffffffu, incl, off);
        if (lane >= off) incl += t;
    }
    if (lane == 31) sw[w] = incl;
    __syncthreads();
    int wofs = 0;
    if (tid < 8) {
        int t = sw[tid];
        int e = 0;
        for (int k = 0; k < 8; k++) { int tv = __shfl_sync(0xffu, t, k); if (k < tid) e += tv; }
        sw[tid] = e;
        (void)e;
    }
    __syncthreads();
    wofs = sw[w];
    int texcl = wofs + incl - s;                 // exclusive across block
    int blkofs = g_part[blockIdx.x];
#pragma unroll
    for (int k = 0; k < 8; k++) {
        int i = base + k;
        if (i < n) {
            int p = blkofs + texcl + v[k];
            g_rowptr[i] = p;
            g_cursor[i] = p;
        }
    }
}

__global__ void k_fill(const int* __restrict__ ei, int E) {
    int e = blockIdx.x * 256 + threadIdx.x;
    if (e < E) {
        int s = ei[e];
        int d = ei[E + e];
        int pos = atomicAdd(&g_cursor[d], 1);
        g_csrc[pos] = s;
    }
}

// ---------------- M = Wq @ Wk^T  (64x64), SMEM-staged ----------------------------
__global__ void __launch_bounds__(1024) k_M(const float* __restrict__ Wq,
                                            const float* __restrict__ Wk) {
    __shared__ float sq[64 * 64];
    __shared__ float sk[64 * 64];
    int tid = threadIdx.x;
    for (int i = tid; i < 4096; i += 1024) { sq[i] = Wq[i]; sk[i] = Wk[i]; }
    __syncthreads();
    int idx = blockIdx.x * 1024 + tid;
    int d = idx >> 6, j = idx & 63;
    float acc = 0.f;
#pragma unroll
    for (int e = 0; e < 64; e++) acc = fmaf(sq[d * 64 + e], sk[j * 64 + e], acc);
    g_M[idx] = acc;
}

// ---------------- tall-skinny GEMM (8x8 register tile, f32x2) --------------------
// g_T[row,64] = (A[row,K] @ W[K,64]) * dinv[row].
// 256 thr: t=tid&7 owns 8 cols, g=tid>>3 owns 4 rows. ROWS=128/block.
// K processed in 64-wide chunks to stay within 48KB static smem.
template <int K>
__global__ void __launch_bounds__(256) k_gemm8(const float* __restrict__ Aext,
                                               int srcLayer,
                                               const float* __restrict__ W,
                                               int nrows) {
    constexpr int NCH = K / 64;
    __shared__ float shW[64 * 64];   // 16KB (one 64-k chunk of W)
    __shared__ float shA[128 * 64];  // 32KB (128 rows x 64-k chunk)
    int tid = threadIdx.x;
    int t = tid & 7, g = tid >> 3;
    int rowBase = blockIdx.x * 128;

    const float* A = (srcLayer < 0) ? Aext : (g_H + (size_t)srcLayer * nrows * 64);
    const float4* A4 = (const float4*)A;
    const float4* W4 = (const float4*)W;
    const int q = K / 4;

    u64 acc[4][4];
#pragma unroll
    for (int rr = 0; rr < 4; rr++)
#pragma unroll
        for (int p = 0; p < 4; p++) acc[rr][p] = 0ull;

    for (int ch = 0; ch < NCH; ch++) {
        if (ch > 0) __syncthreads();
        {
            float4* sW4 = (float4*)shW;
            for (int i = tid; i < 1024; i += 256) sW4[i] = W4[ch * 1024 + i];
        }
        {
            float4* sA4 = (float4*)shA;
            for (int i = tid; i < 128 * 16; i += 256) {
                int r = i >> 4;
                int row = rowBase + r;
                float4 v = make_float4(0.f, 0.f, 0.f, 0.f);
                if (row < nrows) v = A4[(size_t)row * q + ch * 16 + (i & 15)];
                sA4[i] = v;
            }
        }
        __syncthreads();

#pragma unroll 4
        for (int k = 0; k < 64; k += 4) {
            ulonglong2 w0a = *(const ulonglong2*)&shW[(k + 0) * 64 + t * 8];
            ulonglong2 w0b = *(const ulonglong2*)&shW[(k + 0) * 64 + t * 8 + 4];
            ulonglong2 w1a = *(const ulonglong2*)&shW[(k + 1) * 64 + t * 8];
            ulonglong2 w1b = *(const ulonglong2*)&shW[(k + 1) * 64 + t * 8 + 4];
            ulonglong2 w2a = *(const ulonglong2*)&shW[(k + 2) * 64 + t * 8];
            ulonglong2 w2b = *(const ulonglong2*)&shW[(k + 2) * 64 + t * 8 + 4];
            ulonglong2 w3a = *(const ulonglong2*)&shW[(k + 3) * 64 + t * 8];
            ulonglong2 w3b = *(const ulonglong2*)&shW[(k + 3) * 64 + t * 8 + 4];
#pragma unroll
            for (int rr = 0; rr < 4; rr++) {
                float4 a4 = *(const float4*)&shA[(g * 4 + rr) * 64 + k];
                u64 a0 = pk2(a4.x);
                fma2(acc[rr][0], a0, w0a.x); fma2(acc[rr][1], a0, w0a.y);
                fma2(acc[rr][2], a0, w0b.x); fma2(acc[rr][3], a0, w0b.y);
                u64 a1 = pk2(a4.y);
                fma2(acc[rr][0], a1, w1a.x); fma2(acc[rr][1], a1, w1a.y);
                fma2(acc[rr][2], a1, w1b.x); fma2(acc[rr][3], a1, w1b.y);
                u64 a2 = pk2(a4.z);
                fma2(acc[rr][0], a2, w2a.x); fma2(acc[rr][1], a2, w2a.y);
                fma2(acc[rr][2], a2, w2b.x); fma2(acc[rr][3], a2, w2b.y);
                u64 a3 = pk2(a4.w);
                fma2(acc[rr][0], a3, w3a.x); fma2(acc[rr][1], a3, w3a.y);
                fma2(acc[rr][2], a3, w3b.x); fma2(acc[rr][3], a3, w3b.y);
            }
        }
    }

#pragma unroll
    for (int rr = 0; rr < 4; rr++) {
        int row = rowBase + g * 4 + rr;
        if (row < nrows) {
            float dv = g_dinv[row];
            float4 v0, v1;
            unpk2(acc[rr][0], v0.x, v0.y);
            unpk2(acc[rr][1], v0.z, v0.w);
            unpk2(acc[rr][2], v1.x, v1.y);
            unpk2(acc[rr][3], v1.z, v1.w);
            v0.x *= dv; v0.y *= dv; v0.z *= dv; v0.w *= dv;
            v1.x *= dv; v1.y *= dv; v1.z *= dv; v1.w *= dv;
            ((float4*)g_T)[(size_t)row * 16 + t * 2]     = v0;
            ((float4*)g_T)[(size_t)row * 16 + t * 2 + 1] = v1;
        }
    }
}

// ---------------- scores: 8x8-tile GEMM + fused dot ------------------------------
// s[row] = ((H[row] @ M) . H[row]) / TEMP. Same tiling as k_gemm8, K=64.
__global__ void __launch_bounds__(256) k_score(int nitems) {
    __shared__ float shW[64 * 64];
    __shared__ float shA[128 * 64];
    int tid = threadIdx.x;
    int t = tid & 7, g = tid >> 3;
    int rowBase = blockIdx.x * 128;

    {
        float4* sW4 = (float4*)shW;
        const float4* M4 = (const float4*)g_M;
        for (int i = tid; i < 1024; i += 256) sW4[i] = M4[i];
    }
    {
        float4* sA4 = (float4*)shA;
        const float4* A4 = (const float4*)g_H;
        for (int i = tid; i < 128 * 16; i += 256) {
            int r = i >> 4;
            int row = rowBase + r;
            float4 v = make_float4(0.f, 0.f, 0.f, 0.f);
            if (row < nitems) v = A4[(size_t)row * 16 + (i & 15)];
            sA4[i] = v;
        }
    }
    __syncthreads();

    u64 acc[4][4];
#pragma unroll
    for (int rr = 0; rr < 4; rr++)
#pragma unroll
        for (int p = 0; p < 4; p++) acc[rr][p] = 0ull;

#pragma unroll 4
    for (int k = 0; k < 64; k += 4) {
        ulonglong2 w0a = *(const ulonglong2*)&shW[(k + 0) * 64 + t * 8];
        ulonglong2 w0b = *(const ulonglong2*)&shW[(k + 0) * 64 + t * 8 + 4];
        ulonglong2 w1a = *(const ulonglong2*)&shW[(k + 1) * 64 + t * 8];
        ulonglong2 w1b = *(const ulonglong2*)&shW[(k + 1) * 64 + t * 8 + 4];
        ulonglong2 w2a = *(const ulonglong2*)&shW[(k + 2) * 64 + t * 8];
        ulonglong2 w2b = *(const ulonglong2*)&shW[(k + 2) * 64 + t * 8 + 4];
        ulonglong2 w3a = *(const ulonglong2*)&shW[(k + 3) * 64 + t * 8];
        ulonglong2 w3b = *(const ulonglong2*)&shW[(k + 3) * 64 + t * 8 + 4];
#pragma unroll
        for (int rr = 0; rr < 4; rr++) {
            float4 a4 = *(const float4*)&shA[(g * 4 + rr) * 64 + k];
            u64 a0 = pk2(a4.x);
            fma2(acc[rr][0], a0, w0a.x); fma2(acc[rr][1], a0, w0a.y);
            fma2(acc[rr][2], a0, w0b.x); fma2(acc[rr][3], a0, w0b.y);
            u64 a1 = pk2(a4.y);
            fma2(acc[rr][0], a1, w1a.x); fma2(acc[rr][1], a1, w1a.y);
            fma2(acc[rr][2], a1, w1b.x); fma2(acc[rr][3], a1, w1b.y);
            u64 a2 = pk2(a4.z);
            fma2(acc[rr][0], a2, w2a.x); fma2(acc[rr][1], a2, w2a.y);
            fma2(acc[rr][2], a2, w2b.x); fma2(acc[rr][3], a2, w2b.y);
            u64 a3 = pk2(a4.w);
            fma2(acc[rr][0], a3, w3a.x); fma2(acc[rr][1], a3, w3a.y);
            fma2(acc[rr][2], a3, w3b.x); fma2(acc[rr][3], a3, w3b.y);
        }
    }

    // epilogue: dot P[row, t*8..t*8+7] with H[row, same cols]; reduce across 8 t-lanes
#pragma unroll
    for (int rr = 0; rr < 4; rr++) {
        int row = rowBase + g * 4 + rr;
        float4 h0 = *(const float4*)&shA[(g * 4 + rr) * 64 + t * 8];
        float4 h1 = *(const float4*)&shA[(g * 4 + rr) * 64 + t * 8 + 4];
        float4 p0, p1;
        unpk2(acc[rr][0], p0.x, p0.y);
        unpk2(acc[rr][1], p0.z, p0.w);
        unpk2(acc[rr][2], p1.x, p1.y);
        unpk2(acc[rr][3], p1.z, p1.w);
        float p = p0.x * h0.x + p0.y * h0.y + p0.z * h0.z + p0.w * h0.w
                + p1.x * h1.x + p1.y * h1.y + p1.z * h1.z + p1.w * h1.w;
        p += __shfl_xor_sync(0xffffffffu, p, 1);
        p += __shfl_xor_sync(0xffffffffu, p, 2);
        p += __shfl_xor_sync(0xffffffffu, p, 4);
        if (t == 0 && row < nitems) g_scores[row] = p * 10.0f;  // 1/TEMP
    }
}

// ---------------- CSR gather propagate + bias + relu, fused ----------------------
__global__ void __launch_bounds__(256) k_gather(int layer, const float* __restrict__ b,
                                                int n) {
    int warp = (blockIdx.x * 256 + threadIdx.x) >> 5;
    int lane = threadIdx.x & 31;
    if (warp >= n) return;
    int start = g_rowptr[warp];
    int end = g_rowptr[warp + 1];
    const float2* T2 = (const float2*)g_T;
    float2 a = T2[(size_t)warp * 32 + lane];      // Ts[d]
    int j = start;
    for (; j + 8 <= end; j += 8) {
        int s0 = g_csrc[j],     s1 = g_csrc[j + 1], s2 = g_csrc[j + 2], s3 = g_csrc[j + 3];
        int s4 = g_csrc[j + 4], s5 = g_csrc[j + 5], s6 = g_csrc[j + 6], s7 = g_csrc[j + 7];
        float2 v0 = T2[(size_t)s0 * 32 + lane];
        float2 v1 = T2[(size_t)s1 * 32 + lane];
        float2 v2 = T2[(size_t)s2 * 32 + lane];
        float2 v3 = T2[(size_t)s3 * 32 + lane];
        float2 v4 = T2[(size_t)s4 * 32 + lane];
        float2 v5 = T2[(size_t)s5 * 32 + lane];
        float2 v6 = T2[(size_t)s6 * 32 + lane];
        float2 v7 = T2[(size_t)s7 * 32 + lane];
        a.x += ((v0.x + v1.x) + (v2.x + v3.x)) + ((v4.x + v5.x) + (v6.x + v7.x));
        a.y += ((v0.y + v1.y) + (v2.y + v3.y)) + ((v4.y + v5.y) + (v6.y + v7.y));
    }
    for (; j < end; j++) {
        int s = g_csrc[j];
        float2 v = T2[(size_t)s * 32 + lane];
        a.x += v.x;
        a.y += v.y;
    }
    float dv = g_dinv[warp];
    float2 bb = ((const float2*)b)[lane];
    float2 h;
    h.x = fmaxf(fmaf(a.x, dv, bb.x), 0.f);
    h.y = fmaxf(fmaf(a.y, dv, bb.y), 0.f);
    ((float2*)g_H)[(size_t)layer * n * 32 + (size_t)warp * 32 + lane] = h;
}

// ---------------- fused softmax + weighted sum + output GEMM ---------------------
__global__ void __launch_bounds__(128) k_final(const float* __restrict__ Wout,
                                               const float* __restrict__ bout,
                                               float* __restrict__ out, int n) {
    __shared__ float shW[64 * 40];
    __shared__ float shB[40];
    __shared__ float shS[16][64];
    int tid = threadIdx.x;
    for (int i = tid; i < 64 * 40; i += 128) shW[i] = Wout[i];
    if (tid < 40) shB[tid] = bout[tid];

    int nodeBase = blockIdx.x * 16;
    int nl = tid >> 3;
    int dg = tid & 7;
    int node = nodeBase + nl;
    if (node < n) {
        float s0 = g_scores[node];
        float s1 = g_scores[n + node];
        float s2 = g_scores[2 * n + node];
        float s3 = g_scores[3 * n + node];
        float m = fmaxf(fmaxf(s0, s1), fmaxf(s2, s3));
        float e0 = __expf(s0 - m), e1 = __expf(s1 - m);
        float e2 = __expf(s2 - m), e3 = __expf(s3 - m);
        float inv = 1.0f / (e0 + e1 + e2 + e3);
        e0 *= inv; e1 *= inv; e2 *= inv; e3 *= inv;
        size_t nh = (size_t)n * 64;
        size_t off0 = (size_t)node * 64 + dg * 8;
#pragma unroll
        for (int dd = 0; dd < 8; dd++) {
            size_t o = off0 + dd;
            float v = e0 * g_H[o] + e1 * g_H[nh + o] + e2 * g_H[2 * nh + o] + e3 * g_H[3 * nh + o];
            shS[nl][dg * 8 + dd] = v;
        }
    }
    __syncthreads();

    for (int o = tid; o < 16 * 40; o += 128) {
        int n2 = o / 40, c = o - n2 * 40;
        int node2 = nodeBase + n2;
        if (node2 < n) {
            float acc = shB[c];
#pragma unroll
            for (int k = 0; k < 64; k++) acc = fmaf(shS[n2][k], shW[k * 40 + c], acc);
            out[(size_t)node2 * 40 + c] = acc;
        }
    }
}

// ---------------- launch ---------------------------------------------------------
extern "C" void kernel_launch(void* const* d_in, const int* in_sizes, int n_in,
                              void* d_out, int out_size) {
    const float* x    = (const float*)d_in[0];
    const int*   ei   = (const int*)d_in[1];   // int32 on device
    const float* W0   = (const float*)d_in[2];
    const float* b0   = (const float*)d_in[3];
    const float* Ws   = (const float*)d_in[4];
    const float* bs   = (const float*)d_in[5];
    const float* Wq   = (const float*)d_in[6];
    const float* Wk   = (const float*)d_in[7];
    const float* Wout = (const float*)d_in[8];
    const float* bout = (const float*)d_in[9];
    float* out        = (float*)d_out;

    int n = in_sizes[0] / 128;
    int E = in_sizes[1] / 2;
    int nparts = (n + SCAN_BLK - 1) / SCAN_BLK;
    int gemmBlocks = (n + 127) / 128;

    // ordered so the K=128 GEMM sits at the index ncu sampled in recent rounds
    k_zerocnt<<<(n + 255) / 256, 256>>>(n);                 // 0
    k_count<<<(E + 255) / 256, 256>>>(ei, E);               // 1
    k_scan1<<<nparts, 256>>>(n);                            // 2 (also writes dinv)
    k_gemm8<128><<<gemmBlocks, 256>>>(x, -1, W0, n);        // 3  <- hoping profiled
    k_scan2<<<1, MAX_PARTS>>>(nparts, n);                   // 4
    k_scan3<<<nparts, 256>>>(n);                            // 5
    k_fill<<<(E + 255) / 256, 256>>>(ei, E);                // 6
    k_M<<<4, 1024>>>(Wq, Wk);                               // 7

    int gatherBlocks = (n * 32 + 255) / 256;

    for (int l = 0; l < 4; l++) {
        if (l > 0) {
            k_gemm8<64><<<gemmBlocks, 256>>>(nullptr, l - 1,
                                             Ws + (size_t)(l - 1) * 64 * 64, n);
        }
        const float* b = (l == 0) ? b0 : (bs + (size_t)(l - 1) * 64);
        k_gather<<<gatherBlocks, 256>>>(l, b, n);
    }

    int nitems = 4 * n;
    k_score<<<(nitems + 127) / 128, 256>>>(nitems);
    k_final<<<(n + 15) / 16, 128>>>(Wout, bout, out, n);
}

// round 12
// speedup vs baseline: 1.2687x; 1.2687x over previous
#include <cuda_runtime.h>
#include <cstdint>

#define NN 100000
#define EE 1600000
#define SCAN_BLK 2048          // elements per scan block (256 threads x 8)
#define MAX_PARTS 128

typedef unsigned long long u64;

// f32x2 packed helpers (sm_100+): bit-exact 2-wide fp32 FMA, 2x FFMA throughput
__device__ __forceinline__ u64 pk2(float x) {
    u64 r; asm("mov.b64 %0, {%1, %1};" : "=l"(r) : "f"(x)); return r;
}
__device__ __forceinline__ void fma2(u64& d, u64 a, u64 b) {
    asm("fma.rn.f32x2 %0, %1, %2, %0;" : "+l"(d) : "l"(a), "l"(b));
}
__device__ __forceinline__ void unpk2(u64 v, float& lo, float& hi) {
    asm("mov.b64 {%0, %1}, %2;" : "=f"(lo), "=f"(hi) : "l"(v));
}

// ---------------- scratch (device globals; no allocations allowed) -------------
__device__ int   g_cnt[NN];            // in-degree (edges only)
__device__ int   g_rowptr[NN + 1];     // CSR row pointers (by dst)
__device__ int   g_cursor[NN];         // fill cursors
__device__ int   g_csrc[EE];           // CSR src indices
__device__ int   g_part[MAX_PARTS];    // scan partials
__device__ float g_dinv[NN];
__device__ float g_T[NN * 64];         // Ts = (h @ W) * dinv[row]
__device__ float g_H[4 * NN * 64];     // per-layer post-relu features
__device__ float g_M[64 * 64];         // Wq @ Wk^T
__device__ float g_scores[4 * NN];

// ---------------- degree / CSR build --------------------------------------------
__global__ void k_zerocnt(int n) {
    int i = blockIdx.x * 256 + threadIdx.x;
    if (i < n) g_cnt[i] = 0;
}

__global__ void k_count(const int* __restrict__ ei, int E) {
    int e = blockIdx.x * 256 + threadIdx.x;
    if (e < E) atomicAdd(&g_cnt[ei[E + e]], 1);
}

// ---- scan phase 1: per-block reduce + dinv  -------------------------------------
__global__ void __launch_bounds__(256) k_scan1(int n) {
    int tid = threadIdx.x;
    int base = blockIdx.x * SCAN_BLK + tid * 8;
    int s = 0;
#pragma unroll
    for (int k = 0; k < 8; k++) {
        int i = base + k;
        if (i < n) {
            int c = g_cnt[i];
            s += c;
            g_dinv[i] = rsqrtf((float)(c + 1));   // +1 self loop
        }
    }
#pragma unroll
    for (int off = 16; off; off >>= 1) s += __shfl_xor_sync(0xffffffffu, s, off);
    __shared__ int sw[8];
    if ((tid & 31) == 0) sw[tid >> 5] = s;
    __syncthreads();
    if (tid == 0) {
        int t = 0;
#pragma unroll
        for (int w = 0; w < 8; w++) t += sw[w];
        g_part[blockIdx.x] = t;
    }
}

// ---- scan phase 2: exclusive scan of partials (single small block) --------------
__global__ void k_scan2(int nparts, int n) {
    __shared__ int sh[MAX_PARTS];
    int tid = threadIdx.x;
    sh[tid] = (tid < nparts) ? g_part[tid] : 0;
    __syncthreads();
    for (int off = 1; off < MAX_PARTS; off <<= 1) {
        int t = (tid >= off) ? sh[tid - off] : 0;
        __syncthreads();
        sh[tid] += t;
        __syncthreads();
    }
    if (tid < nparts) g_part[tid] = (tid ? sh[tid - 1] : 0);
    if (tid == MAX_PARTS - 1) g_rowptr[n] = sh[MAX_PARTS - 1];
}

// ---- scan phase 3: block-local exclusive scan + offset -> rowptr/cursor ---------
__global__ void __launch_bounds__(256) k_scan3(int n) {
    __shared__ int sw[8];
    int tid = threadIdx.x;
    int base = blockIdx.x * SCAN_BLK + tid * 8;
    int v[8];
    int s = 0;
#pragma unroll
    for (int k = 0; k < 8; k++) {
        int i = base + k;
        int c = (i < n) ? g_cnt[i] : 0;
        v[k] = s;          // exclusive within thread
        s += c;
    }
    int lane = tid & 31, w = tid >> 5;
    int incl = s;
#pragma unroll
    for (int off = 1; off < 32; off <<= 1) {
        int t = __shfl_up_sync(0xffffffffu, incl, off);
        if (lane >= off) incl += t;
    }
    if (lane == 31) sw[w] = incl;
    __syncthreads();
    int wofs = 0;
    if (tid < 8) {
        int t = sw[tid];
        int e = 0;
        for (int k = 0; k < 8; k++) { int tv = __shfl_sync(0xffu, t, k); if (k < tid) e += tv; }
        sw[tid] = e;
        (void)e;
    }
    __syncthreads();
    wofs = sw[w];
    int texcl = wofs + incl - s;                 // exclusive across block
    int blkofs = g_part[blockIdx.x];
#pragma unroll
    for (int k = 0; k < 8; k++) {
        int i = base + k;
        if (i < n) {
            int p = blkofs + texcl + v[k];
            g_rowptr[i] = p;
            g_cursor[i] = p;
        }
    }
}

__global__ void k_fill(const int* __restrict__ ei, int E) {
    int e = blockIdx.x * 256 + threadIdx.x;
    if (e < E) {
        int s = ei[e];
        int d = ei[E + e];
        int pos = atomicAdd(&g_cursor[d], 1);
        g_csrc[pos] = s;
    }
}

// ---------------- M = Wq @ Wk^T  (64x64), SMEM-staged ----------------------------
__global__ void __launch_bounds__(1024) k_M(const float* __restrict__ Wq,
                                            const float* __restrict__ Wk) {
    __shared__ float sq[64 * 64];
    __shared__ float sk[64 * 64];
    int tid = threadIdx.x;
    for (int i = tid; i < 4096; i += 1024) { sq[i] = Wq[i]; sk[i] = Wk[i]; }
    __syncthreads();
    int idx = blockIdx.x * 1024 + tid;
    int d = idx >> 6, j = idx & 63;
    float acc = 0.f;
#pragma unroll
    for (int e = 0; e < 64; e++) acc = fmaf(sq[d * 64 + e], sk[j * 64 + e], acc);
    g_M[idx] = acc;
}

// ---------------- tall-skinny GEMM (f32x2, 16 cols x RPG rows) -------------------
// g_T[row,64] = (A[row,K] @ W[K,64]) * dinv[row].
// t=tid&15 owns 4 cols; g=tid>>4 owns RPG rows; ROWS=RPG*16 rows per block.
template <int K, int RPG>
__global__ void __launch_bounds__(256) k_gemm(const float* __restrict__ Aext,
                                              int srcLayer,
                                              const float* __restrict__ W,
                                              int nrows) {
    constexpr int ROWS = RPG * 16;
    __shared__ float shW[K * 64];
    __shared__ float shA[ROWS * K];
    int tid = threadIdx.x;

    const float* A = (srcLayer < 0) ? Aext : (g_H + (size_t)srcLayer * nrows * 64);

    {
        const float4* W4 = (const float4*)W;
        float4* sW4 = (float4*)shW;
        for (int i = tid; i < K * 16; i += 256) sW4[i] = W4[i];
    }
    int rowBase = blockIdx.x * ROWS;
    {
        float4* sA4 = (float4*)shA;
        const float4* A4 = (const float4*)A;
        const int q = K / 4;
        for (int i = tid; i < ROWS * q; i += 256) {
            int r = i / q;
            int row = rowBase + r;
            float4 v = make_float4(0.f, 0.f, 0.f, 0.f);
            if (row < nrows) v = A4[(size_t)row * q + (i - r * q)];
            sA4[i] = v;
        }
    }
    __syncthreads();

    int t = tid & 15, g = tid >> 4;
    u64 acc[RPG][2];
#pragma unroll
    for (int rr = 0; rr < RPG; rr++) { acc[rr][0] = 0ull; acc[rr][1] = 0ull; }

#pragma unroll 4
    for (int k = 0; k < K; k += 4) {
        ulonglong2 w0 = *(const ulonglong2*)&shW[(k + 0) * 64 + t * 4];
        ulonglong2 w1 = *(const ulonglong2*)&shW[(k + 1) * 64 + t * 4];
        ulonglong2 w2 = *(const ulonglong2*)&shW[(k + 2) * 64 + t * 4];
        ulonglong2 w3 = *(const ulonglong2*)&shW[(k + 3) * 64 + t * 4];
#pragma unroll
        for (int rr = 0; rr < RPG; rr++) {
            float4 a4 = *(const float4*)&shA[(g * RPG + rr) * K + k];
            u64 a0 = pk2(a4.x), a1 = pk2(a4.y), a2 = pk2(a4.z), a3 = pk2(a4.w);
            fma2(acc[rr][0], a0, w0.x); fma2(acc[rr][1], a0, w0.y);
            fma2(acc[rr][0], a1, w1.x); fma2(acc[rr][1], a1, w1.y);
            fma2(acc[rr][0], a2, w2.x); fma2(acc[rr][1], a2, w2.y);
            fma2(acc[rr][0], a3, w3.x); fma2(acc[rr][1], a3, w3.y);
        }
    }

#pragma unroll
    for (int rr = 0; rr < RPG; rr++) {
        int row = rowBase + g * RPG + rr;
        if (row < nrows) {
            float dv = g_dinv[row];
            float4 v;
            unpk2(acc[rr][0], v.x, v.y);
            unpk2(acc[rr][1], v.z, v.w);
            v.x *= dv; v.y *= dv; v.z *= dv; v.w *= dv;
            ((float4*)g_T)[(size_t)row * 16 + t] = v;
        }
    }
}

// ---------------- scores as GEMM (f32x2, RPG=8) + fused dot ----------------------
__global__ void __launch_bounds__(256) k_score(int nitems) {
    constexpr int K = 64, RPG = 8, ROWS = 128;
    __shared__ float shW[K * 64];
    __shared__ float shA[ROWS * K];
    int tid = threadIdx.x;

    {
        float4* sW4 = (float4*)shW;
        const float4* M4 = (const float4*)g_M;
        for (int i = tid; i < K * 16; i += 256) sW4[i] = M4[i];
    }
    int rowBase = blockIdx.x * ROWS;
    {
        float4* sA4 = (float4*)shA;
        const float4* A4 = (const float4*)g_H;
        for (int i = tid; i < ROWS * 16; i += 256) {
            int r = i >> 4;
            int row = rowBase + r;
            float4 v = make_float4(0.f, 0.f, 0.f, 0.f);
            if (row < nitems) v = A4[(size_t)row * 16 + (i & 15)];
            sA4[i] = v;
        }
    }
    __syncthreads();

    int t = tid & 15, g = tid >> 4;
    u64 acc[RPG][2];
#pragma unroll
    for (int rr = 0; rr < RPG; rr++) { acc[rr][0] = 0ull; acc[rr][1] = 0ull; }

#pragma unroll 4
    for (int k = 0; k < K; k += 4) {
        ulonglong2 w0 = *(const ulonglong2*)&shW[(k + 0) * 64 + t * 4];
        ulonglong2 w1 = *(const ulonglong2*)&shW[(k + 1) * 64 + t * 4];
        ulonglong2 w2 = *(const ulonglong2*)&shW[(k + 2) * 64 + t * 4];
        ulonglong2 w3 = *(const ulonglong2*)&shW[(k + 3) * 64 + t * 4];
#pragma unroll
        for (int rr = 0; rr < RPG; rr++) {
            float4 a4 = *(const float4*)&shA[(g * RPG + rr) * K + k];
            u64 a0 = pk2(a4.x), a1 = pk2(a4.y), a2 = pk2(a4.z), a3 = pk2(a4.w);
            fma2(acc[rr][0], a0, w0.x); fma2(acc[rr][1], a0, w0.y);
            fma2(acc[rr][0], a1, w1.x); fma2(acc[rr][1], a1, w1.y);
            fma2(acc[rr][0], a2, w2.x); fma2(acc[rr][1], a2, w2.y);
            fma2(acc[rr][0], a3, w3.x); fma2(acc[rr][1], a3, w3.y);
        }
    }

#pragma unroll
    for (int rr = 0; rr < RPG; rr++) {
        int row = rowBase + g * RPG + rr;
        float4 h4 = *(const float4*)&shA[(g * RPG + rr) * K + t * 4];
        float4 pv;
        unpk2(acc[rr][0], pv.x, pv.y);
        unpk2(acc[rr][1], pv.z, pv.w);
        float p = pv.x * h4.x + pv.y * h4.y + pv.z * h4.z + pv.w * h4.w;
        p += __shfl_xor_sync(0xffffffffu, p, 1);
        p += __shfl_xor_sync(0xffffffffu, p, 2);
        p += __shfl_xor_sync(0xffffffffu, p, 4);
        p += __shfl_xor_sync(0xffffffffu, p, 8);
        if (t == 0 && row < nitems) g_scores[row] = p * 10.0f;  // 1/TEMP
    }
}

// ---------------- CSR gather propagate + bias + relu, fused ----------------------
__global__ void __launch_bounds__(256) k_gather(int layer, const float* __restrict__ b,
                                                int n) {
    int warp = (blockIdx.x * 256 + threadIdx.x) >> 5;
    int lane = threadIdx.x & 31;
    if (warp >= n) return;
    int start = g_rowptr[warp];
    int end = g_rowptr[warp + 1];
    const float2* T2 = (const float2*)g_T;
    float2 a = T2[(size_t)warp * 32 + lane];      // Ts[d]
    int j = start;
    for (; j + 8 <= end; j += 8) {
        int s0 = g_csrc[j],     s1 = g_csrc[j + 1], s2 = g_csrc[j + 2], s3 = g_csrc[j + 3];
        int s4 = g_csrc[j + 4], s5 = g_csrc[j + 5], s6 = g_csrc[j + 6], s7 = g_csrc[j + 7];
        float2 v0 = T2[(size_t)s0 * 32 + lane];
        float2 v1 = T2[(size_t)s1 * 32 + lane];
        float2 v2 = T2[(size_t)s2 * 32 + lane];
        float2 v3 = T2[(size_t)s3 * 32 + lane];
        float2 v4 = T2[(size_t)s4 * 32 + lane];
        float2 v5 = T2[(size_t)s5 * 32 + lane];
        float2 v6 = T2[(size_t)s6 * 32 + lane];
        float2 v7 = T2[(size_t)s7 * 32 + lane];
        a.x += ((v0.x + v1.x) + (v2.x + v3.x)) + ((v4.x + v5.x) + (v6.x + v7.x));
        a.y += ((v0.y + v1.y) + (v2.y + v3.y)) + ((v4.y + v5.y) + (v6.y + v7.y));
    }
    for (; j < end; j++) {
        int s = g_csrc[j];
        float2 v = T2[(size_t)s * 32 + lane];
        a.x += v.x;
        a.y += v.y;
    }
    float dv = g_dinv[warp];
    float2 bb = ((const float2*)b)[lane];
    float2 h;
    h.x = fmaxf(fmaf(a.x, dv, bb.x), 0.f);
    h.y = fmaxf(fmaf(a.y, dv, bb.y), 0.f);
    ((float2*)g_H)[(size_t)layer * n * 32 + (size_t)warp * 32 + lane] = h;
}

// ---------------- fused softmax + weighted sum + output GEMM ---------------------
__global__ void __launch_bounds__(128) k_final(const float* __restrict__ Wout,
                                               const float* __restrict__ bout,
                                               float* __restrict__ out, int n) {
    __shared__ float shW[64 * 40];
    __shared__ float shB[40];
    __shared__ float shS[16][64];
    int tid = threadIdx.x;
    for (int i = tid; i < 64 * 40; i += 128) shW[i] = Wout[i];
    if (tid < 40) shB[tid] = bout[tid];

    int nodeBase = blockIdx.x * 16;
    int nl = tid >> 3;
    int dg = tid & 7;
    int node = nodeBase + nl;
    if (node < n) {
        float s0 = g_scores[node];
        float s1 = g_scores[n + node];
        float s2 = g_scores[2 * n + node];
        float s3 = g_scores[3 * n + node];
        float m = fmaxf(fmaxf(s0, s1), fmaxf(s2, s3));
        float e0 = __expf(s0 - m), e1 = __expf(s1 - m);
        float e2 = __expf(s2 - m), e3 = __expf(s3 - m);
        float inv = 1.0f / (e0 + e1 + e2 + e3);
        e0 *= inv; e1 *= inv; e2 *= inv; e3 *= inv;
        size_t nh = (size_t)n * 64;
        size_t off0 = (size_t)node * 64 + dg * 8;
#pragma unroll
        for (int dd = 0; dd < 8; dd++) {
            size_t o = off0 + dd;
            float v = e0 * g_H[o] + e1 * g_H[nh + o] + e2 * g_H[2 * nh + o] + e3 * g_H[3 * nh + o];
            shS[nl][dg * 8 + dd] = v;
        }
    }
    __syncthreads();

    for (int o = tid; o < 16 * 40; o += 128) {
        int n2 = o / 40, c = o - n2 * 40;
        int node2 = nodeBase + n2;
        if (node2 < n) {
            float acc = shB[c];
#pragma unroll
            for (int k = 0; k < 64; k++) acc = fmaf(shS[n2][k], shW[k * 40 + c], acc);
            out[(size_t)node2 * 40 + c] = acc;
        }
    }
}

// ---------------- launch ---------------------------------------------------------
extern "C" void kernel_launch(void* const* d_in, const int* in_sizes, int n_in,
                              void* d_out, int out_size) {
    const float* x    = (const float*)d_in[0];
    const int*   ei   = (const int*)d_in[1];   // int32 on device
    const float* W0   = (const float*)d_in[2];
    const float* b0   = (const float*)d_in[3];
    const float* Ws   = (const float*)d_in[4];
    const float* bs   = (const float*)d_in[5];
    const float* Wq   = (const float*)d_in[6];
    const float* Wk   = (const float*)d_in[7];
    const float* Wout = (const float*)d_in[8];
    const float* bout = (const float*)d_in[9];
    float* out        = (float*)d_out;

    int n = in_sizes[0] / 128;
    int E = in_sizes[1] / 2;
    int nparts = (n + SCAN_BLK - 1) / SCAN_BLK;

    // ordered so the K=128 GEMM sits at the slot ncu samples (slot 3)
    k_zerocnt<<<(n + 255) / 256, 256>>>(n);                 // 0
    k_count<<<(E + 255) / 256, 256>>>(ei, E);               // 1
    k_scan1<<<nparts, 256>>>(n);                            // 2 (also writes dinv)
    k_gemm<128, 4><<<(n + 63) / 64, 256>>>(x, -1, W0, n);   // 3  <- profiled
    k_scan2<<<1, MAX_PARTS>>>(nparts, n);                   // 4
    k_scan3<<<nparts, 256>>>(n);                            // 5
    k_fill<<<(E + 255) / 256, 256>>>(ei, E);                // 6
    k_M<<<4, 1024>>>(Wq, Wk);                               // 7

    int gatherBlocks = (n * 32 + 255) / 256;

    for (int l = 0; l < 4; l++) {
        if (l > 0) {
            k_gemm<64, 8><<<(n + 127) / 128, 256>>>(nullptr, l - 1,
                                                    Ws + (size_t)(l - 1) * 64 * 64, n);
        }
        const float* b = (l == 0) ? b0 : (bs + (size_t)(l - 1) * 64);
        k_gather<<<gatherBlocks, 256>>>(l, b, n);
    }

    int nitems = 4 * n;
    k_score<<<(nitems + 127) / 128, 256>>>(nitems);
    k_final<<<(n + 15) / 16, 128>>>(Wout, bout, out, n);
}

// round 13
// speedup vs baseline: 1.2783x; 1.0075x over previous
#include <cuda_runtime.h>
#include <cstdint>

#define NN 100000
#define EE 1600000
#define SCAN_BLK 2048          // elements per scan block (256 threads x 8)
#define MAX_PARTS 128

typedef unsigned long long u64;

// f32x2 packed helpers (sm_100+): bit-exact 2-wide fp32 FMA, 2x FFMA throughput
__device__ __forceinline__ u64 pk2(float x) {
    u64 r; asm("mov.b64 %0, {%1, %1};" : "=l"(r) : "f"(x)); return r;
}
__device__ __forceinline__ void fma2(u64& d, u64 a, u64 b) {
    asm("fma.rn.f32x2 %0, %1, %2, %0;" : "+l"(d) : "l"(a), "l"(b));
}
__device__ __forceinline__ void unpk2(u64 v, float& lo, float& hi) {
    asm("mov.b64 {%0, %1}, %2;" : "=f"(lo), "=f"(hi) : "l"(v));
}

// ---------------- scratch (device globals; no allocations allowed) -------------
__device__ int   g_cnt[NN];            // in-degree (edges only)
__device__ int   g_rowptr[NN + 1];     // CSR row pointers (by dst)
__device__ int   g_cursor[NN];         // fill cursors
__device__ int   g_csrc[EE];           // CSR src indices
__device__ int   g_part[MAX_PARTS];    // scan partials
__device__ float g_dinv[NN];
__device__ float g_T[NN * 64];         // Ts = (h @ W) * dinv[row]
__device__ float g_H[4 * NN * 64];     // per-layer post-relu features
__device__ float g_M[64 * 64];         // Wq @ Wk^T
__device__ float g_scores[4 * NN];

// ---------------- degree / CSR build --------------------------------------------
__global__ void k_zerocnt(int n) {
    int i = blockIdx.x * 256 + threadIdx.x;
    if (i < n) g_cnt[i] = 0;
}

__global__ void k_count(const int* __restrict__ ei, int E) {
    int e = blockIdx.x * 256 + threadIdx.x;
    if (e < E) atomicAdd(&g_cnt[ei[E + e]], 1);
}

// ---- scan phase 1: per-block reduce + dinv  -------------------------------------
__global__ void __launch_bounds__(256) k_scan1(int n) {
    int tid = threadIdx.x;
    int base = blockIdx.x * SCAN_BLK + tid * 8;
    int s = 0;
#pragma unroll
    for (int k = 0; k < 8; k++) {
        int i = base + k;
        if (i < n) {
            int c = g_cnt[i];
            s += c;
            g_dinv[i] = rsqrtf((float)(c + 1));   // +1 self loop
        }
    }
#pragma unroll
    for (int off = 16; off; off >>= 1) s += __shfl_xor_sync(0xffffffffu, s, off);
    __shared__ int sw[8];
    if ((tid & 31) == 0) sw[tid >> 5] = s;
    __syncthreads();
    if (tid == 0) {
        int t = 0;
#pragma unroll
        for (int w = 0; w < 8; w++) t += sw[w];
        g_part[blockIdx.x] = t;
    }
}

// ---- scan phase 2: exclusive scan of partials (single small block) --------------
__global__ void k_scan2(int nparts, int n) {
    __shared__ int sh[MAX_PARTS];
    int tid = threadIdx.x;
    sh[tid] = (tid < nparts) ? g_part[tid] : 0;
    __syncthreads();
    for (int off = 1; off < MAX_PARTS; off <<= 1) {
        int t = (tid >= off) ? sh[tid - off] : 0;
        __syncthreads();
        sh[tid] += t;
        __syncthreads();
    }
    if (tid < nparts) g_part[tid] = (tid ? sh[tid - 1] : 0);
    if (tid == MAX_PARTS - 1) g_rowptr[n] = sh[MAX_PARTS - 1];
}

// ---- scan phase 3: block-local exclusive scan + offset -> rowptr/cursor ---------
__global__ void __launch_bounds__(256) k_scan3(int n) {
    __shared__ int sw[8];
    int tid = threadIdx.x;
    int base = blockIdx.x * SCAN_BLK + tid * 8;
    int v[8];
    int s = 0;
#pragma unroll
    for (int k = 0; k < 8; k++) {
        int i = base + k;
        int c = (i < n) ? g_cnt[i] : 0;
        v[k] = s;          // exclusive within thread
        s += c;
    }
    int lane = tid & 31, w = tid >> 5;
    int incl = s;
#pragma unroll
    for (int off = 1; off < 32; off <<= 1) {
        int t = __shfl_up_sync(0xffffffffu, incl, off);
        if (lane >= off) incl += t;
    }
    if (lane == 31) sw[w] = incl;
    __syncthreads();
    int wofs = 0;
    if (tid < 8) {
        int t = sw[tid];
        int e = 0;
        for (int k = 0; k < 8; k++) { int tv = __shfl_sync(0xffu, t, k); if (k < tid) e += tv; }
        sw[tid] = e;
        (void)e;
    }
    __syncthreads();
    wofs = sw[w];
    int texcl = wofs + incl - s;                 // exclusive across block
    int blkofs = g_part[blockIdx.x];
#pragma unroll
    for (int k = 0; k < 8; k++) {
        int i = base + k;
        if (i < n) {
            int p = blkofs + texcl + v[k];
            g_rowptr[i] = p;
            g_cursor[i] = p;
        }
    }
}

__global__ void k_fill(const int* __restrict__ ei, int E) {
    int e = blockIdx.x * 256 + threadIdx.x;
    if (e < E) {
        int s = ei[e];
        int d = ei[E + e];
        int pos = atomicAdd(&g_cursor[d], 1);
        g_csrc[pos] = s;
    }
}

// ---------------- M = Wq @ Wk^T  (64x64), SMEM-staged ----------------------------
__global__ void __launch_bounds__(1024) k_M(const float* __restrict__ Wq,
                                            const float* __restrict__ Wk) {
    __shared__ float sq[64 * 64];
    __shared__ float sk[64 * 64];
    int tid = threadIdx.x;
    for (int i = tid; i < 4096; i += 1024) { sq[i] = Wq[i]; sk[i] = Wk[i]; }
    __syncthreads();
    int idx = blockIdx.x * 1024 + tid;
    int d = idx >> 6, j = idx & 63;
    float acc = 0.f;
#pragma unroll
    for (int e = 0; e < 64; e++) acc = fmaf(sq[d * 64 + e], sk[j * 64 + e], acc);
    g_M[idx] = acc;
}

// ---------------- tall-skinny GEMM (f32x2, 16 cols x 4 rows, K chunked) ----------
// g_T[row,64] = (A[row,K] @ W[K,64]) * dinv[row].
// t=tid&15 owns 4 cols; g=tid>>4 owns 4 rows; 64 rows/block; K in 64-wide chunks.
// 32KB smem + <=51 regs (minBlocks 5) -> ~40 resident warps/SM.
template <int K>
__global__ void __launch_bounds__(256, 5) k_gemm(const float* __restrict__ Aext,
                                                 int srcLayer,
                                                 const float* __restrict__ W,
                                                 int nrows) {
    constexpr int NCH = K / 64;
    __shared__ float shW[64 * 64];   // 16KB: one 64-k chunk of W
    __shared__ float shA[64 * 64];   // 16KB: 64 rows x 64-k chunk
    int tid = threadIdx.x;
    int t = tid & 15, g = tid >> 4;
    int rowBase = blockIdx.x * 64;

    const float* A = (srcLayer < 0) ? Aext : (g_H + (size_t)srcLayer * nrows * 64);
    const float4* A4 = (const float4*)A;
    const float4* W4 = (const float4*)W;
    const int q = K / 4;

    u64 acc[4][2];
#pragma unroll
    for (int rr = 0; rr < 4; rr++) { acc[rr][0] = 0ull; acc[rr][1] = 0ull; }

    for (int ch = 0; ch < NCH; ch++) {
        if (ch > 0) __syncthreads();
        {
            float4* sW4 = (float4*)shW;
            for (int i = tid; i < 1024; i += 256) sW4[i] = W4[ch * 1024 + i];
        }
        {
            float4* sA4 = (float4*)shA;
            for (int i = tid; i < 1024; i += 256) {
                int r = i >> 4;
                int row = rowBase + r;
                float4 v = make_float4(0.f, 0.f, 0.f, 0.f);
                if (row < nrows) v = A4[(size_t)row * q + ch * 16 + (i & 15)];
                sA4[i] = v;
            }
        }
        __syncthreads();

#pragma unroll 4
        for (int k = 0; k < 64; k += 4) {
            ulonglong2 w0 = *(const ulonglong2*)&shW[(k + 0) * 64 + t * 4];
            ulonglong2 w1 = *(const ulonglong2*)&shW[(k + 1) * 64 + t * 4];
            ulonglong2 w2 = *(const ulonglong2*)&shW[(k + 2) * 64 + t * 4];
            ulonglong2 w3 = *(const ulonglong2*)&shW[(k + 3) * 64 + t * 4];
#pragma unroll
            for (int rr = 0; rr < 4; rr++) {
                float4 a4 = *(const float4*)&shA[(g * 4 + rr) * 64 + k];
                u64 a0 = pk2(a4.x), a1 = pk2(a4.y), a2 = pk2(a4.z), a3 = pk2(a4.w);
                fma2(acc[rr][0], a0, w0.x); fma2(acc[rr][1], a0, w0.y);
                fma2(acc[rr][0], a1, w1.x); fma2(acc[rr][1], a1, w1.y);
                fma2(acc[rr][0], a2, w2.x); fma2(acc[rr][1], a2, w2.y);
                fma2(acc[rr][0], a3, w3.x); fma2(acc[rr][1], a3, w3.y);
            }
        }
    }

#pragma unroll
    for (int rr = 0; rr < 4; rr++) {
        int row = rowBase + g * 4 + rr;
        if (row < nrows) {
            float dv = g_dinv[row];
            float4 v;
            unpk2(acc[rr][0], v.x, v.y);
            unpk2(acc[rr][1], v.z, v.w);
            v.x *= dv; v.y *= dv; v.z *= dv; v.w *= dv;
            ((float4*)g_T)[(size_t)row * 16 + t] = v;
        }
    }
}

// ---------------- scores as GEMM (f32x2) + fused dot, 64 rows/block --------------
__global__ void __launch_bounds__(256, 5) k_score(int nitems) {
    __shared__ float shW[64 * 64];
    __shared__ float shA[64 * 64];
    int tid = threadIdx.x;
    int t = tid & 15, g = tid >> 4;
    int rowBase = blockIdx.x * 64;

    {
        float4* sW4 = (float4*)shW;
        const float4* M4 = (const float4*)g_M;
        for (int i = tid; i < 1024; i += 256) sW4[i] = M4[i];
    }
    {
        float4* sA4 = (float4*)shA;
        const float4* A4 = (const float4*)g_H;
        for (int i = tid; i < 1024; i += 256) {
            int r = i >> 4;
            int row = rowBase + r;
            float4 v = make_float4(0.f, 0.f, 0.f, 0.f);
            if (row < nitems) v = A4[(size_t)row * 16 + (i & 15)];
            sA4[i] = v;
        }
    }
    __syncthreads();

    u64 acc[4][2];
#pragma unroll
    for (int rr = 0; rr < 4; rr++) { acc[rr][0] = 0ull; acc[rr][1] = 0ull; }

#pragma unroll 4
    for (int k = 0; k < 64; k += 4) {
        ulonglong2 w0 = *(const ulonglong2*)&shW[(k + 0) * 64 + t * 4];
        ulonglong2 w1 = *(const ulonglong2*)&shW[(k + 1) * 64 + t * 4];
        ulonglong2 w2 = *(const ulonglong2*)&shW[(k + 2) * 64 + t * 4];
        ulonglong2 w3 = *(const ulonglong2*)&shW[(k + 3) * 64 + t * 4];
#pragma unroll
        for (int rr = 0; rr < 4; rr++) {
            float4 a4 = *(const float4*)&shA[(g * 4 + rr) * 64 + k];
            u64 a0 = pk2(a4.x), a1 = pk2(a4.y), a2 = pk2(a4.z), a3 = pk2(a4.w);
            fma2(acc[rr][0], a0, w0.x); fma2(acc[rr][1], a0, w0.y);
            fma2(acc[rr][0], a1, w1.x); fma2(acc[rr][1], a1, w1.y);
            fma2(acc[rr][0], a2, w2.x); fma2(acc[rr][1], a2, w2.y);
            fma2(acc[rr][0], a3, w3.x); fma2(acc[rr][1], a3, w3.y);
        }
    }

#pragma unroll
    for (int rr = 0; rr < 4; rr++) {
        int row = rowBase + g * 4 + rr;
        float4 h4 = *(const float4*)&shA[(g * 4 + rr) * 64 + t * 4];
        float4 pv;
        unpk2(acc[rr][0], pv.x, pv.y);
        unpk2(acc[rr][1], pv.z, pv.w);
        float p = pv.x * h4.x + pv.y * h4.y + pv.z * h4.z + pv.w * h4.w;
        p += __shfl_xor_sync(0xffffffffu, p, 1);
        p += __shfl_xor_sync(0xffffffffu, p, 2);
        p += __shfl_xor_sync(0xffffffffu, p, 4);
        p += __shfl_xor_sync(0xffffffffu, p, 8);
        if (t == 0 && row < nitems) g_scores[row] = p * 10.0f;  // 1/TEMP
    }
}

// ---------------- CSR gather propagate + bias + relu, fused ----------------------
__global__ void __launch_bounds__(256) k_gather(int layer, const float* __restrict__ b,
                                                int n) {
    int warp = (blockIdx.x * 256 + threadIdx.x) >> 5;
    int lane = threadIdx.x & 31;
    if (warp >= n) return;
    int start = g_rowptr[warp];
    int end = g_rowptr[warp + 1];
    const float2* T2 = (const float2*)g_T;
    float2 a = T2[(size_t)warp * 32 + lane];      // Ts[d]
    int j = start;
    for (; j + 8 <= end; j += 8) {
        int s0 = g_csrc[j],     s1 = g_csrc[j + 1], s2 = g_csrc[j + 2], s3 = g_csrc[j + 3];
        int s4 = g_csrc[j + 4], s5 = g_csrc[j + 5], s6 = g_csrc[j + 6], s7 = g_csrc[j + 7];
        float2 v0 = T2[(size_t)s0 * 32 + lane];
        float2 v1 = T2[(size_t)s1 * 32 + lane];
        float2 v2 = T2[(size_t)s2 * 32 + lane];
        float2 v3 = T2[(size_t)s3 * 32 + lane];
        float2 v4 = T2[(size_t)s4 * 32 + lane];
        float2 v5 = T2[(size_t)s5 * 32 + lane];
        float2 v6 = T2[(size_t)s6 * 32 + lane];
        float2 v7 = T2[(size_t)s7 * 32 + lane];
        a.x += ((v0.x + v1.x) + (v2.x + v3.x)) + ((v4.x + v5.x) + (v6.x + v7.x));
        a.y += ((v0.y + v1.y) + (v2.y + v3.y)) + ((v4.y + v5.y) + (v6.y + v7.y));
    }
    for (; j < end; j++) {
        int s = g_csrc[j];
        float2 v = T2[(size_t)s * 32 + lane];
        a.x += v.x;
        a.y += v.y;
    }
    float dv = g_dinv[warp];
    float2 bb = ((const float2*)b)[lane];
    float2 h;
    h.x = fmaxf(fmaf(a.x, dv, bb.x), 0.f);
    h.y = fmaxf(fmaf(a.y, dv, bb.y), 0.f);
    ((float2*)g_H)[(size_t)layer * n * 32 + (size_t)warp * 32 + lane] = h;
}

// ---------------- fused softmax + weighted sum + output GEMM ---------------------
__global__ void __launch_bounds__(128) k_final(const float* __restrict__ Wout,
                                               const float* __restrict__ bout,
                                               float* __restrict__ out, int n) {
    __shared__ float shW[64 * 40];
    __shared__ float shB[40];
    __shared__ float shS[16][64];
    int tid = threadIdx.x;
    for (int i = tid; i < 64 * 40; i += 128) shW[i] = Wout[i];
    if (tid < 40) shB[tid] = bout[tid];

    int nodeBase = blockIdx.x * 16;
    int nl = tid >> 3;
    int dg = tid & 7;
    int node = nodeBase + nl;
    if (node < n) {
        float s0 = g_scores[node];
        float s1 = g_scores[n + node];
        float s2 = g_scores[2 * n + node];
        float s3 = g_scores[3 * n + node];
        float m = fmaxf(fmaxf(s0, s1), fmaxf(s2, s3));
        float e0 = __expf(s0 - m), e1 = __expf(s1 - m);
        float e2 = __expf(s2 - m), e3 = __expf(s3 - m);
        float inv = 1.0f / (e0 + e1 + e2 + e3);
        e0 *= inv; e1 *= inv; e2 *= inv; e3 *= inv;
        size_t nh = (size_t)n * 64;
        size_t off0 = (size_t)node * 64 + dg * 8;
#pragma unroll
        for (int dd = 0; dd < 8; dd++) {
            size_t o = off0 + dd;
            float v = e0 * g_H[o] + e1 * g_H[nh + o] + e2 * g_H[2 * nh + o] + e3 * g_H[3 * nh + o];
            shS[nl][dg * 8 + dd] = v;
        }
    }
    __syncthreads();

    for (int o = tid; o < 16 * 40; o += 128) {
        int n2 = o / 40, c = o - n2 * 40;
        int node2 = nodeBase + n2;
        if (node2 < n) {
            float acc = shB[c];
#pragma unroll
            for (int k = 0; k < 64; k++) acc = fmaf(shS[n2][k], shW[k * 40 + c], acc);
            out[(size_t)node2 * 40 + c] = acc;
        }
    }
}

// ---------------- launch ---------------------------------------------------------
extern "C" void kernel_launch(void* const* d_in, const int* in_sizes, int n_in,
                              void* d_out, int out_size) {
    const float* x    = (const float*)d_in[0];
    const int*   ei   = (const int*)d_in[1];   // int32 on device
    const float* W0   = (const float*)d_in[2];
    const float* b0   = (const float*)d_in[3];
    const float* Ws   = (const float*)d_in[4];
    const float* bs   = (const float*)d_in[5];
    const float* Wq   = (const float*)d_in[6];
    const float* Wk   = (const float*)d_in[7];
    const float* Wout = (const float*)d_in[8];
    const float* bout = (const float*)d_in[9];
    float* out        = (float*)d_out;

    int n = in_sizes[0] / 128;
    int E = in_sizes[1] / 2;
    int nparts = (n + SCAN_BLK - 1) / SCAN_BLK;
    int gemmBlocks = (n + 63) / 64;

    // ordered so the K=128 GEMM sits at the slot ncu samples
    k_zerocnt<<<(n + 255) / 256, 256>>>(n);                 // 0
    k_count<<<(E + 255) / 256, 256>>>(ei, E);               // 1
    k_scan1<<<nparts, 256>>>(n);                            // 2 (also writes dinv)
    k_gemm<128><<<gemmBlocks, 256>>>(x, -1, W0, n);         // 3  <- profiled
    k_scan2<<<1, MAX_PARTS>>>(nparts, n);                   // 4
    k_scan3<<<nparts, 256>>>(n);                            // 5
    k_fill<<<(E + 255) / 256, 256>>>(ei, E);                // 6
    k_M<<<4, 1024>>>(Wq, Wk);                               // 7

    int gatherBlocks = (n * 32 + 255) / 256;

    for (int l = 0; l < 4; l++) {
        if (l > 0) {
            k_gemm<64><<<gemmBlocks, 256>>>(nullptr, l - 1,
                                            Ws + (size_t)(l - 1) * 64 * 64, n);
        }
        const float* b = (l == 0) ? b0 : (bs + (size_t)(l - 1) * 64);
        k_gather<<<gatherBlocks, 256>>>(l, b, n);
    }

    int nitems = 4 * n;
    k_score<<<(nitems + 63) / 64, 256>>>(nitems);
    k_final<<<(n + 15) / 16, 128>>>(Wout, bout, out, n);
}

// round 14
// speedup vs baseline: 1.3164x; 1.0298x over previous
#include <cuda_runtime.h>
#include <cstdint>

#define NN 100000
#define EE 1600000
#define SCAN_BLK 2048          // elements per scan block (256 threads x 8)
#define MAX_PARTS 128

typedef unsigned long long u64;

// f32x2 packed helpers (sm_100+): bit-exact 2-wide fp32 FMA, 2x FFMA throughput
__device__ __forceinline__ u64 pk2(float x) {
    u64 r; asm("mov.b64 %0, {%1, %1};" : "=l"(r) : "f"(x)); return r;
}
__device__ __forceinline__ void fma2(u64& d, u64 a, u64 b) {
    asm("fma.rn.f32x2 %0, %1, %2, %0;" : "+l"(d) : "l"(a), "l"(b));
}
__device__ __forceinline__ void unpk2(u64 v, float& lo, float& hi) {
    asm("mov.b64 {%0, %1}, %2;" : "=f"(lo), "=f"(hi) : "l"(v));
}

// ---------------- scratch (device globals; no allocations allowed) -------------
__device__ int   g_cnt[NN];            // in-degree (edges only)
__device__ int   g_rowptr[NN + 1];     // CSR row pointers (by dst)
__device__ int   g_cursor[NN];         // fill cursors
__device__ int   g_csrc[EE];           // CSR src indices
__device__ int   g_part[MAX_PARTS];    // scan partials
__device__ float g_dinv[NN];
__device__ float g_T[NN * 64];         // Ts = (h @ W) * dinv[row]
__device__ float g_H[4 * NN * 64];     // per-layer post-relu features
__device__ float g_M[64 * 64];         // Wq @ Wk^T
__device__ float g_scores[4 * NN];

// ---------------- degree / CSR build --------------------------------------------
__global__ void k_zerocnt(int n) {
    int i = blockIdx.x * 256 + threadIdx.x;
    if (i < n) g_cnt[i] = 0;
}

__global__ void k_count(const int* __restrict__ ei, int E) {
    int e = blockIdx.x * 256 + threadIdx.x;
    if (e < E) atomicAdd(&g_cnt[ei[E + e]], 1);
}

// ---- scan phase 1: per-block reduce + dinv  -------------------------------------
__global__ void __launch_bounds__(256) k_scan1(int n) {
    int tid = threadIdx.x;
    int base = blockIdx.x * SCAN_BLK + tid * 8;
    int s = 0;
#pragma unroll
    for (int k = 0; k < 8; k++) {
        int i = base + k;
        if (i < n) {
            int c = g_cnt[i];
            s += c;
            g_dinv[i] = rsqrtf((float)(c + 1));   // +1 self loop
        }
    }
#pragma unroll
    for (int off = 16; off; off >>= 1) s += __shfl_xor_sync(0xffffffffu, s, off);
    __shared__ int sw[8];
    if ((tid & 31) == 0) sw[tid >> 5] = s;
    __syncthreads();
    if (tid == 0) {
        int t = 0;
#pragma unroll
        for (int w = 0; w < 8; w++) t += sw[w];
        g_part[blockIdx.x] = t;
    }
}

// ---- scan phase 2: exclusive scan of partials (single small block) --------------
__global__ void k_scan2(int nparts, int n) {
    __shared__ int sh[MAX_PARTS];
    int tid = threadIdx.x;
    sh[tid] = (tid < nparts) ? g_part[tid] : 0;
    __syncthreads();
    for (int off = 1; off < MAX_PARTS; off <<= 1) {
        int t = (tid >= off) ? sh[tid - off] : 0;
        __syncthreads();
        sh[tid] += t;
        __syncthreads();
    }
    if (tid < nparts) g_part[tid] = (tid ? sh[tid - 1] : 0);
    if (tid == MAX_PARTS - 1) g_rowptr[n] = sh[MAX_PARTS - 1];
}

// ---- scan phase 3: block-local exclusive scan + offset -> rowptr/cursor ---------
__global__ void __launch_bounds__(256) k_scan3(int n) {
    __shared__ int sw[8];
    int tid = threadIdx.x;
    int base = blockIdx.x * SCAN_BLK + tid * 8;
    int v[8];
    int s = 0;
#pragma unroll
    for (int k = 0; k < 8; k++) {
        int i = base + k;
        int c = (i < n) ? g_cnt[i] : 0;
        v[k] = s;          // exclusive within thread
        s += c;
    }
    int lane = tid & 31, w = tid >> 5;
    int incl = s;
#pragma unroll
    for (int off = 1; off < 32; off <<= 1) {
        int t = __shfl_up_sync(0xffffffffu, incl, off);
        if (lane >= off) incl += t;
    }
    if (lane == 31) sw[w] = incl;
    __syncthreads();
    int wofs = 0;
    if (tid < 8) {
        int t = sw[tid];
        int e = 0;
        for (int k = 0; k < 8; k++) { int tv = __shfl_sync(0xffu, t, k); if (k < tid) e += tv; }
        sw[tid] = e;
        (void)e;
    }
    __syncthreads();
    wofs = sw[w];
    int texcl = wofs + incl - s;                 // exclusive across block
    int blkofs = g_part[blockIdx.x];
#pragma unroll
    for (int k = 0; k < 8; k++) {
        int i = base + k;
        if (i < n) {
            int p = blkofs + texcl + v[k];
            g_rowptr[i] = p;
            g_cursor[i] = p;
        }
    }
}

__global__ void k_fill(const int* __restrict__ ei, int E) {
    int e = blockIdx.x * 256 + threadIdx.x;
    if (e < E) {
        int s = ei[e];
        int d = ei[E + e];
        int pos = atomicAdd(&g_cursor[d], 1);
        g_csrc[pos] = s;
    }
}

// ---------------- M = Wq @ Wk^T  (64x64), SMEM-staged ----------------------------
__global__ void __launch_bounds__(1024) k_M(const float* __restrict__ Wq,
                                            const float* __restrict__ Wk) {
    __shared__ float sq[64 * 64];
    __shared__ float sk[64 * 64];
    int tid = threadIdx.x;
    for (int i = tid; i < 4096; i += 1024) { sq[i] = Wq[i]; sk[i] = Wk[i]; }
    __syncthreads();
    int idx = blockIdx.x * 1024 + tid;
    int d = idx >> 6, j = idx & 63;
    float acc = 0.f;
#pragma unroll
    for (int e = 0; e < 64; e++) acc = fmaf(sq[d * 64 + e], sk[j * 64 + e], acc);
    g_M[idx] = acc;
}

// ---------------- tall-skinny GEMM (f32x2, 16 cols x 8 rows, K chunked) ----------
// g_T[row,64] = (A[row,K] @ W[K,64]) * dinv[row].
// t=tid&15 owns 4 cols; g=tid>>4 owns 8 rows; 128 rows/block; K in 64-wide chunks.
// W smem reads amortized over 2x rows vs RPG=4 -> L1 wavefronts/FMA drop 33%.
template <int K>
__global__ void __launch_bounds__(256, 4) k_gemm(const float* __restrict__ Aext,
                                                 int srcLayer,
                                                 const float* __restrict__ W,
                                                 int nrows) {
    constexpr int NCH = K / 64;
    __shared__ float shW[64 * 64];    // 16KB: one 64-k chunk of W
    __shared__ float shA[128 * 64];   // 32KB: 128 rows x 64-k chunk
    int tid = threadIdx.x;
    int t = tid & 15, g = tid >> 4;
    int rowBase = blockIdx.x * 128;

    const float* A = (srcLayer < 0) ? Aext : (g_H + (size_t)srcLayer * nrows * 64);
    const float4* A4 = (const float4*)A;
    const float4* W4 = (const float4*)W;
    const int q = K / 4;

    u64 acc[8][2];
#pragma unroll
    for (int rr = 0; rr < 8; rr++) { acc[rr][0] = 0ull; acc[rr][1] = 0ull; }

    for (int ch = 0; ch < NCH; ch++) {
        if (ch > 0) __syncthreads();
        {
            float4* sW4 = (float4*)shW;
            for (int i = tid; i < 1024; i += 256) sW4[i] = W4[ch * 1024 + i];
        }
        {
            float4* sA4 = (float4*)shA;
            for (int i = tid; i < 2048; i += 256) {
                int r = i >> 4;
                int row = rowBase + r;
                float4 v = make_float4(0.f, 0.f, 0.f, 0.f);
                if (row < nrows) v = A4[(size_t)row * q + ch * 16 + (i & 15)];
                sA4[i] = v;
            }
        }
        __syncthreads();

#pragma unroll 4
        for (int k = 0; k < 64; k += 4) {
            ulonglong2 w0 = *(const ulonglong2*)&shW[(k + 0) * 64 + t * 4];
            ulonglong2 w1 = *(const ulonglong2*)&shW[(k + 1) * 64 + t * 4];
            ulonglong2 w2 = *(const ulonglong2*)&shW[(k + 2) * 64 + t * 4];
            ulonglong2 w3 = *(const ulonglong2*)&shW[(k + 3) * 64 + t * 4];
#pragma unroll
            for (int rr = 0; rr < 8; rr++) {
                float4 a4 = *(const float4*)&shA[(g * 8 + rr) * 64 + k];
                u64 a0 = pk2(a4.x), a1 = pk2(a4.y), a2 = pk2(a4.z), a3 = pk2(a4.w);
                fma2(acc[rr][0], a0, w0.x); fma2(acc[rr][1], a0, w0.y);
                fma2(acc[rr][0], a1, w1.x); fma2(acc[rr][1], a1, w1.y);
                fma2(acc[rr][0], a2, w2.x); fma2(acc[rr][1], a2, w2.y);
                fma2(acc[rr][0], a3, w3.x); fma2(acc[rr][1], a3, w3.y);
            }
        }
    }

#pragma unroll
    for (int rr = 0; rr < 8; rr++) {
        int row = rowBase + g * 8 + rr;
        if (row < nrows) {
            float dv = g_dinv[row];
            float4 v;
            unpk2(acc[rr][0], v.x, v.y);
            unpk2(acc[rr][1], v.z, v.w);
            v.x *= dv; v.y *= dv; v.z *= dv; v.w *= dv;
            ((float4*)g_T)[(size_t)row * 16 + t] = v;
        }
    }
}

// ---------------- scores as GEMM (f32x2, 16x8) + fused dot, 128 rows/block -------
__global__ void __launch_bounds__(256, 4) k_score(int nitems) {
    __shared__ float shW[64 * 64];
    __shared__ float shA[128 * 64];
    int tid = threadIdx.x;
    int t = tid & 15, g = tid >> 4;
    int rowBase = blockIdx.x * 128;

    {
        float4* sW4 = (float4*)shW;
        const float4* M4 = (const float4*)g_M;
        for (int i = tid; i < 1024; i += 256) sW4[i] = M4[i];
    }
    {
        float4* sA4 = (float4*)shA;
        const float4* A4 = (const float4*)g_H;
        for (int i = tid; i < 2048; i += 256) {
            int r = i >> 4;
            int row = rowBase + r;
            float4 v = make_float4(0.f, 0.f, 0.f, 0.f);
            if (row < nitems) v = A4[(size_t)row * 16 + (i & 15)];
            sA4[i] = v;
        }
    }
    __syncthreads();

    u64 acc[8][2];
#pragma unroll
    for (int rr = 0; rr < 8; rr++) { acc[rr][0] = 0ull; acc[rr][1] = 0ull; }

#pragma unroll 4
    for (int k = 0; k < 64; k += 4) {
        ulonglong2 w0 = *(const ulonglong2*)&shW[(k + 0) * 64 + t * 4];
        ulonglong2 w1 = *(const ulonglong2*)&shW[(k + 1) * 64 + t * 4];
        ulonglong2 w2 = *(const ulonglong2*)&shW[(k + 2) * 64 + t * 4];
        ulonglong2 w3 = *(const ulonglong2*)&shW[(k + 3) * 64 + t * 4];
#pragma unroll
        for (int rr = 0; rr < 8; rr++) {
            float4 a4 = *(const float4*)&shA[(g * 8 + rr) * 64 + k];
            u64 a0 = pk2(a4.x), a1 = pk2(a4.y), a2 = pk2(a4.z), a3 = pk2(a4.w);
            fma2(acc[rr][0], a0, w0.x); fma2(acc[rr][1], a0, w0.y);
            fma2(acc[rr][0], a1, w1.x); fma2(acc[rr][1], a1, w1.y);
            fma2(acc[rr][0], a2, w2.x); fma2(acc[rr][1], a2, w2.y);
            fma2(acc[rr][0], a3, w3.x); fma2(acc[rr][1], a3, w3.y);
        }
    }

#pragma unroll
    for (int rr = 0; rr < 8; rr++) {
        int row = rowBase + g * 8 + rr;
        float4 h4 = *(const float4*)&shA[(g * 8 + rr) * 64 + t * 4];
        float4 pv;
        unpk2(acc[rr][0], pv.x, pv.y);
        unpk2(acc[rr][1], pv.z, pv.w);
        float p = pv.x * h4.x + pv.y * h4.y + pv.z * h4.z + pv.w * h4.w;
        p += __shfl_xor_sync(0xffffffffu, p, 1);
        p += __shfl_xor_sync(0xffffffffu, p, 2);
        p += __shfl_xor_sync(0xffffffffu, p, 4);
        p += __shfl_xor_sync(0xffffffffu, p, 8);
        if (t == 0 && row < nitems) g_scores[row] = p * 10.0f;  // 1/TEMP
    }
}

// ---------------- CSR gather propagate + bias + relu, fused ----------------------
__global__ void __launch_bounds__(256) k_gather(int layer, const float* __restrict__ b,
                                                int n) {
    int warp = (blockIdx.x * 256 + threadIdx.x) >> 5;
    int lane = threadIdx.x & 31;
    if (warp >= n) return;
    int start = g_rowptr[warp];
    int end = g_rowptr[warp + 1];
    const float2* T2 = (const float2*)g_T;
    float2 a = T2[(size_t)warp * 32 + lane];      // Ts[d]
    int j = start;
    for (; j + 8 <= end; j += 8) {
        int s0 = g_csrc[j],     s1 = g_csrc[j + 1], s2 = g_csrc[j + 2], s3 = g_csrc[j + 3];
        int s4 = g_csrc[j + 4], s5 = g_csrc[j + 5], s6 = g_csrc[j + 6], s7 = g_csrc[j + 7];
        float2 v0 = T2[(size_t)s0 * 32 + lane];
        float2 v1 = T2[(size_t)s1 * 32 + lane];
        float2 v2 = T2[(size_t)s2 * 32 + lane];
        float2 v3 = T2[(size_t)s3 * 32 + lane];
        float2 v4 = T2[(size_t)s4 * 32 + lane];
        float2 v5 = T2[(size_t)s5 * 32 + lane];
        float2 v6 = T2[(size_t)s6 * 32 + lane];
        float2 v7 = T2[(size_t)s7 * 32 + lane];
        a.x += ((v0.x + v1.x) + (v2.x + v3.x)) + ((v4.x + v5.x) + (v6.x + v7.x));
        a.y += ((v0.y + v1.y) + (v2.y + v3.y)) + ((v4.y + v5.y) + (v6.y + v7.y));
    }
    for (; j < end; j++) {
        int s = g_csrc[j];
        float2 v = T2[(size_t)s * 32 + lane];
        a.x += v.x;
        a.y += v.y;
    }
    float dv = g_dinv[warp];
    float2 bb = ((const float2*)b)[lane];
    float2 h;
    h.x = fmaxf(fmaf(a.x, dv, bb.x), 0.f);
    h.y = fmaxf(fmaf(a.y, dv, bb.y), 0.f);
    ((float2*)g_H)[(size_t)layer * n * 32 + (size_t)warp * 32 + lane] = h;
}

// ---------------- fused softmax + weighted sum + output GEMM ---------------------
__global__ void __launch_bounds__(128) k_final(const float* __restrict__ Wout,
                                               const float* __restrict__ bout,
                                               float* __restrict__ out, int n) {
    __shared__ float shW[64 * 40];
    __shared__ float shB[40];
    __shared__ float shS[16][64];
    int tid = threadIdx.x;
    for (int i = tid; i < 64 * 40; i += 128) shW[i] = Wout[i];
    if (tid < 40) shB[tid] = bout[tid];

    int nodeBase = blockIdx.x * 16;
    int nl = tid >> 3;
    int dg = tid & 7;
    int node = nodeBase + nl;
    if (node < n) {
        float s0 = g_scores[node];
        float s1 = g_scores[n + node];
        float s2 = g_scores[2 * n + node];
        float s3 = g_scores[3 * n + node];
        float m = fmaxf(fmaxf(s0, s1), fmaxf(s2, s3));
        float e0 = __expf(s0 - m), e1 = __expf(s1 - m);
        float e2 = __expf(s2 - m), e3 = __expf(s3 - m);
        float inv = 1.0f / (e0 + e1 + e2 + e3);
        e0 *= inv; e1 *= inv; e2 *= inv; e3 *= inv;
        size_t nh = (size_t)n * 64;
        size_t off0 = (size_t)node * 64 + dg * 8;
#pragma unroll
        for (int dd = 0; dd < 8; dd++) {
            size_t o = off0 + dd;
            float v = e0 * g_H[o] + e1 * g_H[nh + o] + e2 * g_H[2 * nh + o] + e3 * g_H[3 * nh + o];
            shS[nl][dg * 8 + dd] = v;
        }
    }
    __syncthreads();

    for (int o = tid; o < 16 * 40; o += 128) {
        int n2 = o / 40, c = o - n2 * 40;
        int node2 = nodeBase + n2;
        if (node2 < n) {
            float acc = shB[c];
#pragma unroll
            for (int k = 0; k < 64; k++) acc = fmaf(shS[n2][k], shW[k * 40 + c], acc);
            out[(size_t)node2 * 40 + c] = acc;
        }
    }
}

// ---------------- launch ---------------------------------------------------------
extern "C" void kernel_launch(void* const* d_in, const int* in_sizes, int n_in,
                              void* d_out, int out_size) {
    const float* x    = (const float*)d_in[0];
    const int*   ei   = (const int*)d_in[1];   // int32 on device
    const float* W0   = (const float*)d_in[2];
    const float* b0   = (const float*)d_in[3];
    const float* Ws   = (const float*)d_in[4];
    const float* bs   = (const float*)d_in[5];
    const float* Wq   = (const float*)d_in[6];
    const float* Wk   = (const float*)d_in[7];
    const float* Wout = (const float*)d_in[8];
    const float* bout = (const float*)d_in[9];
    float* out        = (float*)d_out;

    int n = in_sizes[0] / 128;
    int E = in_sizes[1] / 2;
    int nparts = (n + SCAN_BLK - 1) / SCAN_BLK;
    int gemmBlocks = (n + 127) / 128;

    // ordered so the K=128 GEMM sits at the slot ncu samples
    k_zerocnt<<<(n + 255) / 256, 256>>>(n);                 // 0
    k_count<<<(E + 255) / 256, 256>>>(ei, E);               // 1
    k_scan1<<<nparts, 256>>>(n);                            // 2 (also writes dinv)
    k_gemm<128><<<gemmBlocks, 256>>>(x, -1, W0, n);         // 3  <- profiled
    k_scan2<<<1, MAX_PARTS>>>(nparts, n);                   // 4
    k_scan3<<<nparts, 256>>>(n);                            // 5
    k_fill<<<(E + 255) / 256, 256>>>(ei, E);                // 6
    k_M<<<4, 1024>>>(Wq, Wk);                               // 7

    int gatherBlocks = (n * 32 + 255) / 256;

    for (int l = 0; l < 4; l++) {
        if (l > 0) {
            k_gemm<64><<<gemmBlocks, 256>>>(nullptr, l - 1,
                                            Ws + (size_t)(l - 1) * 64 * 64, n);
        }
        const float* b = (l == 0) ? b0 : (bs + (size_t)(l - 1) * 64);
        k_gather<<<gatherBlocks, 256>>>(l, b, n);
    }

    int nitems = 4 * n;
    k_score<<<(nitems + 127) / 128, 256>>>(nitems);
    k_final<<<(n + 15) / 16, 128>>>(Wout, bout, out, n);
}

// round 15
// speedup vs baseline: 1.4004x; 1.0638x over previous
#include <cuda_runtime.h>
#include <cstdint>

#define NN 100000
#define EE 1600000
#define SCAN_BLK 2048          // elements per scan block (256 threads x 8)
#define MAX_PARTS 128

typedef unsigned long long u64;

// f32x2 packed helpers (sm_100+): bit-exact 2-wide fp32 FMA, 2x FFMA throughput
__device__ __forceinline__ u64 pk2(float x) {
    u64 r; asm("mov.b64 %0, {%1, %1};" : "=l"(r) : "f"(x)); return r;
}
__device__ __forceinline__ void fma2(u64& d, u64 a, u64 b) {
    asm("fma.rn.f32x2 %0, %1, %2, %0;" : "+l"(d) : "l"(a), "l"(b));
}
__device__ __forceinline__ void unpk2(u64 v, float& lo, float& hi) {
    asm("mov.b64 {%0, %1}, %2;" : "=f"(lo), "=f"(hi) : "l"(v));
}

// ---------------- scratch (device globals; no allocations allowed) -------------
__device__ int   g_cnt[NN];            // in-degree (edges only)
__device__ int   g_rowptr[NN + 1];     // CSR row pointers (by dst)
__device__ int   g_cursor[NN];         // fill cursors
__device__ int   g_csrc[EE];           // CSR src indices
__device__ int   g_part[MAX_PARTS];    // scan partials
__device__ float g_dinv[NN];
__device__ float g_T[NN * 64];         // Ts = (h @ W) * dinv[row]
__device__ float g_H[4 * NN * 64];     // per-layer post-relu features
__device__ float g_M[64 * 64];         // Wq @ Wk^T
__device__ float g_scores[4 * NN];

// ---------------- degree / CSR build --------------------------------------------
__global__ void k_zerocnt(int n) {
    int i = blockIdx.x * 256 + threadIdx.x;
    if (i < n) g_cnt[i] = 0;
}

__global__ void k_count(const int* __restrict__ ei, int E) {
    int e = blockIdx.x * 256 + threadIdx.x;
    if (e < E) atomicAdd(&g_cnt[ei[E + e]], 1);
}

// ---- scan phase 1: per-block reduce + dinv  -------------------------------------
__global__ void __launch_bounds__(256) k_scan1(int n) {
    int tid = threadIdx.x;
    int base = blockIdx.x * SCAN_BLK + tid * 8;
    int s = 0;
#pragma unroll
    for (int k = 0; k < 8; k++) {
        int i = base + k;
        if (i < n) {
            int c = g_cnt[i];
            s += c;
            g_dinv[i] = rsqrtf((float)(c + 1));   // +1 self loop
        }
    }
#pragma unroll
    for (int off = 16; off; off >>= 1) s += __shfl_xor_sync(0xffffffffu, s, off);
    __shared__ int sw[8];
    if ((tid & 31) == 0) sw[tid >> 5] = s;
    __syncthreads();
    if (tid == 0) {
        int t = 0;
#pragma unroll
        for (int w = 0; w < 8; w++) t += sw[w];
        g_part[blockIdx.x] = t;
    }
}

// ---- scan phase 2: exclusive scan of partials (single small block) --------------
__global__ void k_scan2(int nparts, int n) {
    __shared__ int sh[MAX_PARTS];
    int tid = threadIdx.x;
    sh[tid] = (tid < nparts) ? g_part[tid] : 0;
    __syncthreads();
    for (int off = 1; off < MAX_PARTS; off <<= 1) {
        int t = (tid >= off) ? sh[tid - off] : 0;
        __syncthreads();
        sh[tid] += t;
        __syncthreads();
    }
    if (tid < nparts) g_part[tid] = (tid ? sh[tid - 1] : 0);
    if (tid == MAX_PARTS - 1) g_rowptr[n] = sh[MAX_PARTS - 1];
}

// ---- scan phase 3: block-local exclusive scan + offset -> rowptr/cursor ---------
__global__ void __launch_bounds__(256) k_scan3(int n) {
    __shared__ int sw[8];
    int tid = threadIdx.x;
    int base = blockIdx.x * SCAN_BLK + tid * 8;
    int v[8];
    int s = 0;
#pragma unroll
    for (int k = 0; k < 8; k++) {
        int i = base + k;
        int c = (i < n) ? g_cnt[i] : 0;
        v[k] = s;          // exclusive within thread
        s += c;
    }
    int lane = tid & 31, w = tid >> 5;
    int incl = s;
#pragma unroll
    for (int off = 1; off < 32; off <<= 1) {
        int t = __shfl_up_sync(0xffffffffu, incl, off);
        if (lane >= off) incl += t;
    }
    if (lane == 31) sw[w] = incl;
    __syncthreads();
    int wofs = 0;
    if (tid < 8) {
        int t = sw[tid];
        int e = 0;
        for (int k = 0; k < 8; k++) { int tv = __shfl_sync(0xffu, t, k); if (k < tid) e += tv; }
        sw[tid] = e;
        (void)e;
    }
    __syncthreads();
    wofs = sw[w];
    int texcl = wofs + incl - s;                 // exclusive across block
    int blkofs = g_part[blockIdx.x];
#pragma unroll
    for (int k = 0; k < 8; k++) {
        int i = base + k;
        if (i < n) {
            int p = blkofs + texcl + v[k];
            g_rowptr[i] = p;
            g_cursor[i] = p;
        }
    }
}

__global__ void k_fill(const int* __restrict__ ei, int E) {
    int e = blockIdx.x * 256 + threadIdx.x;
    if (e < E) {
        int s = ei[e];
        int d = ei[E + e];
        int pos = atomicAdd(&g_cursor[d], 1);
        g_csrc[pos] = s;
    }
}

// ---------------- M = Wq @ Wk^T  (64x64), SMEM-staged ----------------------------
__global__ void __launch_bounds__(1024) k_M(const float* __restrict__ Wq,
                                            const float* __restrict__ Wk) {
    __shared__ float sq[64 * 64];
    __shared__ float sk[64 * 64];
    int tid = threadIdx.x;
    for (int i = tid; i < 4096; i += 1024) { sq[i] = Wq[i]; sk[i] = Wk[i]; }
    __syncthreads();
    int idx = blockIdx.x * 1024 + tid;
    int d = idx >> 6, j = idx & 63;
    float acc = 0.f;
#pragma unroll
    for (int e = 0; e < 64; e++) acc = fmaf(sq[d * 64 + e], sk[j * 64 + e], acc);
    g_M[idx] = acc;
}

// ---------------- tall-skinny GEMM (f32x2, 16 cols x 8 rows, K chunked) ----------
// g_T[row,64] = (A[row,K] @ W[K,64]) * dinv[row].
template <int K>
__global__ void __launch_bounds__(256, 4) k_gemm(const float* __restrict__ Aext,
                                                 int srcLayer,
                                                 const float* __restrict__ W,
                                                 int nrows) {
    constexpr int NCH = K / 64;
    __shared__ float shW[64 * 64];    // 16KB: one 64-k chunk of W
    __shared__ float shA[128 * 64];   // 32KB: 128 rows x 64-k chunk
    int tid = threadIdx.x;
    int t = tid & 15, g = tid >> 4;
    int rowBase = blockIdx.x * 128;

    const float* A = (srcLayer < 0) ? Aext : (g_H + (size_t)srcLayer * nrows * 64);
    const float4* A4 = (const float4*)A;
    const float4* W4 = (const float4*)W;
    const int q = K / 4;

    u64 acc[8][2];
#pragma unroll
    for (int rr = 0; rr < 8; rr++) { acc[rr][0] = 0ull; acc[rr][1] = 0ull; }

    for (int ch = 0; ch < NCH; ch++) {
        if (ch > 0) __syncthreads();
        {
            float4* sW4 = (float4*)shW;
            for (int i = tid; i < 1024; i += 256) sW4[i] = W4[ch * 1024 + i];
        }
        {
            float4* sA4 = (float4*)shA;
            for (int i = tid; i < 2048; i += 256) {
                int r = i >> 4;
                int row = rowBase + r;
                float4 v = make_float4(0.f, 0.f, 0.f, 0.f);
                if (row < nrows) v = A4[(size_t)row * q + ch * 16 + (i & 15)];
                sA4[i] = v;
            }
        }
        __syncthreads();

#pragma unroll 4
        for (int k = 0; k < 64; k += 4) {
            ulonglong2 w0 = *(const ulonglong2*)&shW[(k + 0) * 64 + t * 4];
            ulonglong2 w1 = *(const ulonglong2*)&shW[(k + 1) * 64 + t * 4];
            ulonglong2 w2 = *(const ulonglong2*)&shW[(k + 2) * 64 + t * 4];
            ulonglong2 w3 = *(const ulonglong2*)&shW[(k + 3) * 64 + t * 4];
#pragma unroll
            for (int rr = 0; rr < 8; rr++) {
                float4 a4 = *(const float4*)&shA[(g * 8 + rr) * 64 + k];
                u64 a0 = pk2(a4.x), a1 = pk2(a4.y), a2 = pk2(a4.z), a3 = pk2(a4.w);
                fma2(acc[rr][0], a0, w0.x); fma2(acc[rr][1], a0, w0.y);
                fma2(acc[rr][0], a1, w1.x); fma2(acc[rr][1], a1, w1.y);
                fma2(acc[rr][0], a2, w2.x); fma2(acc[rr][1], a2, w2.y);
                fma2(acc[rr][0], a3, w3.x); fma2(acc[rr][1], a3, w3.y);
            }
        }
    }

#pragma unroll
    for (int rr = 0; rr < 8; rr++) {
        int row = rowBase + g * 8 + rr;
        if (row < nrows) {
            float dv = g_dinv[row];
            float4 v;
            unpk2(acc[rr][0], v.x, v.y);
            unpk2(acc[rr][1], v.z, v.w);
            v.x *= dv; v.y *= dv; v.z *= dv; v.w *= dv;
            ((float4*)g_T)[(size_t)row * 16 + t] = v;
        }
    }
}

// ---------------- scores as GEMM (f32x2, 16x8) + fused dot, per-layer slice ------
// rows [base + blk*128, ...) bounded by limit; absolute row indexes g_H/g_scores.
__global__ void __launch_bounds__(256, 4) k_score(int base, int limit) {
    __shared__ float shW[64 * 64];
    __shared__ float shA[128 * 64];
    int tid = threadIdx.x;
    int t = tid & 15, g = tid >> 4;
    int rowBase = base + blockIdx.x * 128;

    {
        float4* sW4 = (float4*)shW;
        const float4* M4 = (const float4*)g_M;
        for (int i = tid; i < 1024; i += 256) sW4[i] = M4[i];
    }
    {
        float4* sA4 = (float4*)shA;
        const float4* A4 = (const float4*)g_H;
        for (int i = tid; i < 2048; i += 256) {
            int r = i >> 4;
            int row = rowBase + r;
            float4 v = make_float4(0.f, 0.f, 0.f, 0.f);
            if (row < limit) v = A4[(size_t)row * 16 + (i & 15)];
            sA4[i] = v;
        }
    }
    __syncthreads();

    u64 acc[8][2];
#pragma unroll
    for (int rr = 0; rr < 8; rr++) { acc[rr][0] = 0ull; acc[rr][1] = 0ull; }

#pragma unroll 4
    for (int k = 0; k < 64; k += 4) {
        ulonglong2 w0 = *(const ulonglong2*)&shW[(k + 0) * 64 + t * 4];
        ulonglong2 w1 = *(const ulonglong2*)&shW[(k + 1) * 64 + t * 4];
        ulonglong2 w2 = *(const ulonglong2*)&shW[(k + 2) * 64 + t * 4];
        ulonglong2 w3 = *(const ulonglong2*)&shW[(k + 3) * 64 + t * 4];
#pragma unroll
        for (int rr = 0; rr < 8; rr++) {
            float4 a4 = *(const float4*)&shA[(g * 8 + rr) * 64 + k];
            u64 a0 = pk2(a4.x), a1 = pk2(a4.y), a2 = pk2(a4.z), a3 = pk2(a4.w);
            fma2(acc[rr][0], a0, w0.x); fma2(acc[rr][1], a0, w0.y);
            fma2(acc[rr][0], a1, w1.x); fma2(acc[rr][1], a1, w1.y);
            fma2(acc[rr][0], a2, w2.x); fma2(acc[rr][1], a2, w2.y);
            fma2(acc[rr][0], a3, w3.x); fma2(acc[rr][1], a3, w3.y);
        }
    }

#pragma unroll
    for (int rr = 0; rr < 8; rr++) {
        int row = rowBase + g * 8 + rr;
        float4 h4 = *(const float4*)&shA[(g * 8 + rr) * 64 + t * 4];
        float4 pv;
        unpk2(acc[rr][0], pv.x, pv.y);
        unpk2(acc[rr][1], pv.z, pv.w);
        float p = pv.x * h4.x + pv.y * h4.y + pv.z * h4.z + pv.w * h4.w;
        p += __shfl_xor_sync(0xffffffffu, p, 1);
        p += __shfl_xor_sync(0xffffffffu, p, 2);
        p += __shfl_xor_sync(0xffffffffu, p, 4);
        p += __shfl_xor_sync(0xffffffffu, p, 8);
        if (t == 0 && row < limit) g_scores[row] = p * 10.0f;  // 1/TEMP
    }
}

// ---------------- CSR gather propagate + bias + relu, fused ----------------------
__global__ void __launch_bounds__(256) k_gather(int layer, const float* __restrict__ b,
                                                int n) {
    int warp = (blockIdx.x * 256 + threadIdx.x) >> 5;
    int lane = threadIdx.x & 31;
    if (warp >= n) return;
    int start = g_rowptr[warp];
    int end = g_rowptr[warp + 1];
    const float2* T2 = (const float2*)g_T;
    float2 a = T2[(size_t)warp * 32 + lane];      // Ts[d]
    int j = start;
    for (; j + 8 <= end; j += 8) {
        int s0 = g_csrc[j],     s1 = g_csrc[j + 1], s2 = g_csrc[j + 2], s3 = g_csrc[j + 3];
        int s4 = g_csrc[j + 4], s5 = g_csrc[j + 5], s6 = g_csrc[j + 6], s7 = g_csrc[j + 7];
        float2 v0 = T2[(size_t)s0 * 32 + lane];
        float2 v1 = T2[(size_t)s1 * 32 + lane];
        float2 v2 = T2[(size_t)s2 * 32 + lane];
        float2 v3 = T2[(size_t)s3 * 32 + lane];
        float2 v4 = T2[(size_t)s4 * 32 + lane];
        float2 v5 = T2[(size_t)s5 * 32 + lane];
        float2 v6 = T2[(size_t)s6 * 32 + lane];
        float2 v7 = T2[(size_t)s7 * 32 + lane];
        a.x += ((v0.x + v1.x) + (v2.x + v3.x)) + ((v4.x + v5.x) + (v6.x + v7.x));
        a.y += ((v0.y + v1.y) + (v2.y + v3.y)) + ((v4.y + v5.y) + (v6.y + v7.y));
    }
    for (; j < end; j++) {
        int s = g_csrc[j];
        float2 v = T2[(size_t)s * 32 + lane];
        a.x += v.x;
        a.y += v.y;
    }
    float dv = g_dinv[warp];
    float2 bb = ((const float2*)b)[lane];
    float2 h;
    h.x = fmaxf(fmaf(a.x, dv, bb.x), 0.f);
    h.y = fmaxf(fmaf(a.y, dv, bb.y), 0.f);
    ((float2*)g_H)[(size_t)layer * n * 32 + (size_t)warp * 32 + lane] = h;
}

// ---------------- fused softmax + weighted sum + output GEMM ---------------------
__global__ void __launch_bounds__(128) k_final(const float* __restrict__ Wout,
                                               const float* __restrict__ bout,
                                               float* __restrict__ out, int n) {
    __shared__ float shW[64 * 40];
    __shared__ float shB[40];
    __shared__ float shS[16][64];
    int tid = threadIdx.x;
    for (int i = tid; i < 64 * 40; i += 128) shW[i] = Wout[i];
    if (tid < 40) shB[tid] = bout[tid];

    int nodeBase = blockIdx.x * 16;
    int nl = tid >> 3;
    int dg = tid & 7;
    int node = nodeBase + nl;
    if (node < n) {
        float s0 = g_scores[node];
        float s1 = g_scores[n + node];
        float s2 = g_scores[2 * n + node];
        float s3 = g_scores[3 * n + node];
        float m = fmaxf(fmaxf(s0, s1), fmaxf(s2, s3));
        float e0 = __expf(s0 - m), e1 = __expf(s1 - m);
        float e2 = __expf(s2 - m), e3 = __expf(s3 - m);
        float inv = 1.0f / (e0 + e1 + e2 + e3);
        e0 *= inv; e1 *= inv; e2 *= inv; e3 *= inv;
        size_t nh = (size_t)n * 64;
        size_t off0 = (size_t)node * 64 + dg * 8;
#pragma unroll
        for (int dd = 0; dd < 8; dd++) {
            size_t o = off0 + dd;
            float v = e0 * g_H[o] + e1 * g_H[nh + o] + e2 * g_H[2 * nh + o] + e3 * g_H[3 * nh + o];
            shS[nl][dg * 8 + dd] = v;
        }
    }
    __syncthreads();

    for (int o = tid; o < 16 * 40; o += 128) {
        int n2 = o / 40, c = o - n2 * 40;
        int node2 = nodeBase + n2;
        if (node2 < n) {
            float acc = shB[c];
#pragma unroll
            for (int k = 0; k < 64; k++) acc = fmaf(shS[n2][k], shW[k * 40 + c], acc);
            out[(size_t)node2 * 40 + c] = acc;
        }
    }
}

// ---------------- launch (multi-stream fork/join; graph-capture legal) -----------
extern "C" void kernel_launch(void* const* d_in, const int* in_sizes, int n_in,
                              void* d_out, int out_size) {
    const float* x    = (const float*)d_in[0];
    const int*   ei   = (const int*)d_in[1];   // int32 on device
    const float* W0   = (const float*)d_in[2];
    const float* b0   = (const float*)d_in[3];
    const float* Ws   = (const float*)d_in[4];
    const float* bs   = (const float*)d_in[5];
    const float* Wq   = (const float*)d_in[6];
    const float* Wk   = (const float*)d_in[7];
    const float* Wout = (const float*)d_in[8];
    const float* bout = (const float*)d_in[9];
    float* out        = (float*)d_out;

    int n = in_sizes[0] / 128;
    int E = in_sizes[1] / 2;
    int nparts = (n + SCAN_BLK - 1) / SCAN_BLK;
    int gemmBlocks = (n + 127) / 128;
    int gatherBlocks = (n * 32 + 255) / 256;
    int scoreBlocks = (n + 127) / 128;

    // lazily created host resources (not device memory)
    static cudaStream_t s2 = nullptr;
    static cudaEvent_t evStart, evScan1, evFill, evG[3], evS[3];
    if (!s2) {
        cudaStreamCreateWithFlags(&s2, cudaStreamNonBlocking);
        cudaEventCreateWithFlags(&evStart, cudaEventDisableTiming);
        cudaEventCreateWithFlags(&evScan1, cudaEventDisableTiming);
        cudaEventCreateWithFlags(&evFill, cudaEventDisableTiming);
        for (int i = 0; i < 3; i++) {
            cudaEventCreateWithFlags(&evG[i], cudaEventDisableTiming);
            cudaEventCreateWithFlags(&evS[i], cudaEventDisableTiming);
        }
    }

    // ---- main stream: degree + dinv, then gemm0 ----
    k_zerocnt<<<(n + 255) / 256, 256>>>(n);
    k_count<<<(E + 255) / 256, 256>>>(ei, E);
    k_scan1<<<nparts, 256>>>(n);
    cudaEventRecord(evScan1, 0);

    // ---- side stream: k_M + CSR finish (scan2/scan3/fill), overlapping gemm0 ----
    cudaEventRecord(evStart, 0);
    cudaStreamWaitEvent(s2, evStart, 0);
    k_M<<<4, 1024, 0, s2>>>(Wq, Wk);
    cudaStreamWaitEvent(s2, evScan1, 0);
    k_scan2<<<1, MAX_PARTS, 0, s2>>>(nparts, n);
    k_scan3<<<nparts, 256, 0, s2>>>(n);
    k_fill<<<(E + 255) / 256, 256, 0, s2>>>(ei, E);
    cudaEventRecord(evFill, s2);

    k_gemm<128><<<gemmBlocks, 256>>>(x, -1, W0, n);   // overlaps CSR finish

    cudaStreamWaitEvent(0, evFill, 0);

    // ---- layer loop; score_l for l<3 runs on s2 overlapping gemm_{l+1} ----
    for (int l = 0; l < 4; l++) {
        if (l > 0) {
            k_gemm<64><<<gemmBlocks, 256>>>(nullptr, l - 1,
                                            Ws + (size_t)(l - 1) * 64 * 64, n);
        }
        const float* b = (l == 0) ? b0 : (bs + (size_t)(l - 1) * 64);
        k_gather<<<gatherBlocks, 256>>>(l, b, n);
        if (l < 3) {
            cudaEventRecord(evG[l], 0);
            cudaStreamWaitEvent(s2, evG[l], 0);
            k_score<<<scoreBlocks, 256, 0, s2>>>(l * n, (l + 1) * n);
            cudaEventRecord(evS[l], s2);
        }
    }

    // layer-3 scores on main stream
    k_score<<<scoreBlocks, 256>>>(3 * n, 4 * n);

    // join side-stream scores, then final
    for (int i = 0; i < 3; i++) cudaStreamWaitEvent(0, evS[i], 0);
    k_final<<<(n + 15) / 16, 128>>>(Wout, bout, out, n);
}

// round 16
// speedup vs baseline: 1.4111x; 1.0076x over previous
#include <cuda_runtime.h>
#include <cstdint>

#define NN 100000
#define EE 1600000
#define SCAN_BLK 2048          // elements per scan block (256 threads x 8)
#define MAX_PARTS 128

typedef unsigned long long u64;

// f32x2 packed helpers (sm_100+): bit-exact 2-wide fp32 FMA, 2x FFMA throughput
__device__ __forceinline__ u64 pk2(float x) {
    u64 r; asm("mov.b64 %0, {%1, %1};" : "=l"(r) : "f"(x)); return r;
}
__device__ __forceinline__ void fma2(u64& d, u64 a, u64 b) {
    asm("fma.rn.f32x2 %0, %1, %2, %0;" : "+l"(d) : "l"(a), "l"(b));
}
__device__ __forceinline__ void unpk2(u64 v, float& lo, float& hi) {
    asm("mov.b64 {%0, %1}, %2;" : "=f"(lo), "=f"(hi) : "l"(v));
}

// ---------------- scratch (device globals; no allocations allowed) -------------
__device__ int   g_cnt[NN];            // in-degree (edges only)
__device__ int   g_rowptr[NN + 1];     // CSR row pointers (by dst)
__device__ int   g_cursor[NN];         // fill cursors
__device__ int   g_csrc[EE];           // CSR src indices
__device__ int   g_part[MAX_PARTS];    // scan partials
__device__ float g_dinv[NN];
__device__ float g_T[NN * 64];         // Ts = (h @ W) * dinv[row]
__device__ float g_H[4 * NN * 64];     // per-layer post-relu features
__device__ float g_M[64 * 64];         // Wq @ Wk^T
__device__ float g_scores[4 * NN];

// ---------------- degree / CSR build --------------------------------------------
__global__ void k_zerocnt(int n) {
    int i = blockIdx.x * 256 + threadIdx.x;
    if (i < n) g_cnt[i] = 0;
}

__global__ void k_count(const int* __restrict__ ei, int E) {
    int e = blockIdx.x * 256 + threadIdx.x;
    if (e < E) atomicAdd(&g_cnt[ei[E + e]], 1);
}

// ---- scan phase 1: per-block reduce + dinv  -------------------------------------
__global__ void __launch_bounds__(256) k_scan1(int n) {
    int tid = threadIdx.x;
    int base = blockIdx.x * SCAN_BLK + tid * 8;
    int s = 0;
#pragma unroll
    for (int k = 0; k < 8; k++) {
        int i = base + k;
        if (i < n) {
            int c = g_cnt[i];
            s += c;
            g_dinv[i] = rsqrtf((float)(c + 1));   // +1 self loop
        }
    }
#pragma unroll
    for (int off = 16; off; off >>= 1) s += __shfl_xor_sync(0xffffffffu, s, off);
    __shared__ int sw[8];
    if ((tid & 31) == 0) sw[tid >> 5] = s;
    __syncthreads();
    if (tid == 0) {
        int t = 0;
#pragma unroll
        for (int w = 0; w < 8; w++) t += sw[w];
        g_part[blockIdx.x] = t;
    }
}

// ---- scan phase 2: exclusive scan of partials (single small block) --------------
__global__ void k_scan2(int nparts, int n) {
    __shared__ int sh[MAX_PARTS];
    int tid = threadIdx.x;
    sh[tid] = (tid < nparts) ? g_part[tid] : 0;
    __syncthreads();
    for (int off = 1; off < MAX_PARTS; off <<= 1) {
        int t = (tid >= off) ? sh[tid - off] : 0;
        __syncthreads();
        sh[tid] += t;
        __syncthreads();
    }
    if (tid < nparts) g_part[tid] = (tid ? sh[tid - 1] : 0);
    if (tid == MAX_PARTS - 1) g_rowptr[n] = sh[MAX_PARTS - 1];
}

// ---- scan phase 3: block-local exclusive scan + offset -> rowptr/cursor ---------
__global__ void __launch_bounds__(256) k_scan3(int n) {
    __shared__ int sw[8];
    int tid = threadIdx.x;
    int base = blockIdx.x * SCAN_BLK + tid * 8;
    int v[8];
    int s = 0;
#pragma unroll
    for (int k = 0; k < 8; k++) {
        int i = base + k;
        int c = (i < n) ? g_cnt[i] : 0;
        v[k] = s;          // exclusive within thread
        s += c;
    }
    int lane = tid & 31, w = tid >> 5;
    int incl = s;
#pragma unroll
    for (int off = 1; off < 32; off <<= 1) {
        int t = __shfl_up_sync(0xffffffffu, incl, off);
        if (lane >= off) incl += t;
    }
    if (lane == 31) sw[w] = incl;
    __syncthreads();
    int wofs = 0;
    if (tid < 8) {
        int t = sw[tid];
        int e = 0;
        for (int k = 0; k < 8; k++) { int tv = __shfl_sync(0xffu, t, k); if (k < tid) e += tv; }
        sw[tid] = e;
        (void)e;
    }
    __syncthreads();
    wofs = sw[w];
    int texcl = wofs + incl - s;                 // exclusive across block
    int blkofs = g_part[blockIdx.x];
#pragma unroll
    for (int k = 0; k < 8; k++) {
        int i = base + k;
        if (i < n) {
            int p = blkofs + texcl + v[k];
            g_rowptr[i] = p;
            g_cursor[i] = p;
        }
    }
}

__global__ void k_fill(const int* __restrict__ ei, int E) {
    int e = blockIdx.x * 256 + threadIdx.x;
    if (e < E) {
        int s = ei[e];
        int d = ei[E + e];
        int pos = atomicAdd(&g_cursor[d], 1);
        g_csrc[pos] = s;
    }
}

// ---------------- M = Wq @ Wk^T  (64x64), SMEM-staged ----------------------------
__global__ void __launch_bounds__(1024) k_M(const float* __restrict__ Wq,
                                            const float* __restrict__ Wk) {
    __shared__ float sq[64 * 64];
    __shared__ float sk[64 * 64];
    int tid = threadIdx.x;
    for (int i = tid; i < 4096; i += 1024) { sq[i] = Wq[i]; sk[i] = Wk[i]; }
    __syncthreads();
    int idx = blockIdx.x * 1024 + tid;
    int d = idx >> 6, j = idx & 63;
    float acc = 0.f;
#pragma unroll
    for (int e = 0; e < 64; e++) acc = fmaf(sq[d * 64 + e], sk[j * 64 + e], acc);
    g_M[idx] = acc;
}

// ---------------- tall-skinny GEMM (f32x2, 16 cols x 8 rows, row-range) ----------
// g_T[row,64] = (A[row,K] @ W[K,64]) * dinv[row]  for row in [rowStart,rowEnd)
template <int K>
__global__ void __launch_bounds__(256, 4) k_gemm(const float* __restrict__ Aext,
                                                 int srcLayer,
                                                 const float* __restrict__ W,
                                                 int nrows, int rowStart, int rowEnd) {
    constexpr int NCH = K / 64;
    __shared__ float shW[64 * 64];    // 16KB: one 64-k chunk of W
    __shared__ float shA[128 * 64];   // 32KB: 128 rows x 64-k chunk
    int tid = threadIdx.x;
    int t = tid & 15, g = tid >> 4;
    int rowBase = rowStart + blockIdx.x * 128;

    const float* A = (srcLayer < 0) ? Aext : (g_H + (size_t)srcLayer * nrows * 64);
    const float4* A4 = (const float4*)A;
    const float4* W4 = (const float4*)W;
    const int q = K / 4;

    u64 acc[8][2];
#pragma unroll
    for (int rr = 0; rr < 8; rr++) { acc[rr][0] = 0ull; acc[rr][1] = 0ull; }

    for (int ch = 0; ch < NCH; ch++) {
        if (ch > 0) __syncthreads();
        {
            float4* sW4 = (float4*)shW;
            for (int i = tid; i < 1024; i += 256) sW4[i] = W4[ch * 1024 + i];
        }
        {
            float4* sA4 = (float4*)shA;
            for (int i = tid; i < 2048; i += 256) {
                int r = i >> 4;
                int row = rowBase + r;
                float4 v = make_float4(0.f, 0.f, 0.f, 0.f);
                if (row < rowEnd) v = A4[(size_t)row * q + ch * 16 + (i & 15)];
                sA4[i] = v;
            }
        }
        __syncthreads();

#pragma unroll 4
        for (int k = 0; k < 64; k += 4) {
            ulonglong2 w0 = *(const ulonglong2*)&shW[(k + 0) * 64 + t * 4];
            ulonglong2 w1 = *(const ulonglong2*)&shW[(k + 1) * 64 + t * 4];
            ulonglong2 w2 = *(const ulonglong2*)&shW[(k + 2) * 64 + t * 4];
            ulonglong2 w3 = *(const ulonglong2*)&shW[(k + 3) * 64 + t * 4];
#pragma unroll
            for (int rr = 0; rr < 8; rr++) {
                float4 a4 = *(const float4*)&shA[(g * 8 + rr) * 64 + k];
                u64 a0 = pk2(a4.x), a1 = pk2(a4.y), a2 = pk2(a4.z), a3 = pk2(a4.w);
                fma2(acc[rr][0], a0, w0.x); fma2(acc[rr][1], a0, w0.y);
                fma2(acc[rr][0], a1, w1.x); fma2(acc[rr][1], a1, w1.y);
                fma2(acc[rr][0], a2, w2.x); fma2(acc[rr][1], a2, w2.y);
                fma2(acc[rr][0], a3, w3.x); fma2(acc[rr][1], a3, w3.y);
            }
        }
    }

#pragma unroll
    for (int rr = 0; rr < 8; rr++) {
        int row = rowBase + g * 8 + rr;
        if (row < rowEnd) {
            float dv = g_dinv[row];
            float4 v;
            unpk2(acc[rr][0], v.x, v.y);
            unpk2(acc[rr][1], v.z, v.w);
            v.x *= dv; v.y *= dv; v.z *= dv; v.w *= dv;
            ((float4*)g_T)[(size_t)row * 16 + t] = v;
        }
    }
}

// ---------------- scores as GEMM (f32x2, 16x8) + fused dot, per-layer slice ------
__global__ void __launch_bounds__(256, 4) k_score(int base, int limit) {
    __shared__ float shW[64 * 64];
    __shared__ float shA[128 * 64];
    int tid = threadIdx.x;
    int t = tid & 15, g = tid >> 4;
    int rowBase = base + blockIdx.x * 128;

    {
        float4* sW4 = (float4*)shW;
        const float4* M4 = (const float4*)g_M;
        for (int i = tid; i < 1024; i += 256) sW4[i] = M4[i];
    }
    {
        float4* sA4 = (float4*)shA;
        const float4* A4 = (const float4*)g_H;
        for (int i = tid; i < 2048; i += 256) {
            int r = i >> 4;
            int row = rowBase + r;
            float4 v = make_float4(0.f, 0.f, 0.f, 0.f);
            if (row < limit) v = A4[(size_t)row * 16 + (i & 15)];
            sA4[i] = v;
        }
    }
    __syncthreads();

    u64 acc[8][2];
#pragma unroll
    for (int rr = 0; rr < 8; rr++) { acc[rr][0] = 0ull; acc[rr][1] = 0ull; }

#pragma unroll 4
    for (int k = 0; k < 64; k += 4) {
        ulonglong2 w0 = *(const ulonglong2*)&shW[(k + 0) * 64 + t * 4];
        ulonglong2 w1 = *(const ulonglong2*)&shW[(k + 1) * 64 + t * 4];
        ulonglong2 w2 = *(const ulonglong2*)&shW[(k + 2) * 64 + t * 4];
        ulonglong2 w3 = *(const ulonglong2*)&shW[(k + 3) * 64 + t * 4];
#pragma unroll
        for (int rr = 0; rr < 8; rr++) {
            float4 a4 = *(const float4*)&shA[(g * 8 + rr) * 64 + k];
            u64 a0 = pk2(a4.x), a1 = pk2(a4.y), a2 = pk2(a4.z), a3 = pk2(a4.w);
            fma2(acc[rr][0], a0, w0.x); fma2(acc[rr][1], a0, w0.y);
            fma2(acc[rr][0], a1, w1.x); fma2(acc[rr][1], a1, w1.y);
            fma2(acc[rr][0], a2, w2.x); fma2(acc[rr][1], a2, w2.y);
            fma2(acc[rr][0], a3, w3.x); fma2(acc[rr][1], a3, w3.y);
        }
    }

#pragma unroll
    for (int rr = 0; rr < 8; rr++) {
        int row = rowBase + g * 8 + rr;
        float4 h4 = *(const float4*)&shA[(g * 8 + rr) * 64 + t * 4];
        float4 pv;
        unpk2(acc[rr][0], pv.x, pv.y);
        unpk2(acc[rr][1], pv.z, pv.w);
        float p = pv.x * h4.x + pv.y * h4.y + pv.z * h4.z + pv.w * h4.w;
        p += __shfl_xor_sync(0xffffffffu, p, 1);
        p += __shfl_xor_sync(0xffffffffu, p, 2);
        p += __shfl_xor_sync(0xffffffffu, p, 4);
        p += __shfl_xor_sync(0xffffffffu, p, 8);
        if (t == 0 && row < limit) g_scores[row] = p * 10.0f;  // 1/TEMP
    }
}

// ---------------- CSR gather propagate + bias + relu (node range) ----------------
__global__ void __launch_bounds__(256) k_gather(int layer, const float* __restrict__ b,
                                                int n, int nodeStart, int nodeEnd) {
    int warp = nodeStart + ((blockIdx.x * 256 + threadIdx.x) >> 5);
    int lane = threadIdx.x & 31;
    if (warp >= nodeEnd) return;
    int start = g_rowptr[warp];
    int end = g_rowptr[warp + 1];
    const float2* T2 = (const float2*)g_T;
    float2 a = T2[(size_t)warp * 32 + lane];      // Ts[d]
    int j = start;
    for (; j + 8 <= end; j += 8) {
        int s0 = g_csrc[j],     s1 = g_csrc[j + 1], s2 = g_csrc[j + 2], s3 = g_csrc[j + 3];
        int s4 = g_csrc[j + 4], s5 = g_csrc[j + 5], s6 = g_csrc[j + 6], s7 = g_csrc[j + 7];
        float2 v0 = T2[(size_t)s0 * 32 + lane];
        float2 v1 = T2[(size_t)s1 * 32 + lane];
        float2 v2 = T2[(size_t)s2 * 32 + lane];
        float2 v3 = T2[(size_t)s3 * 32 + lane];
        float2 v4 = T2[(size_t)s4 * 32 + lane];
        float2 v5 = T2[(size_t)s5 * 32 + lane];
        float2 v6 = T2[(size_t)s6 * 32 + lane];
        float2 v7 = T2[(size_t)s7 * 32 + lane];
        a.x += ((v0.x + v1.x) + (v2.x + v3.x)) + ((v4.x + v5.x) + (v6.x + v7.x));
        a.y += ((v0.y + v1.y) + (v2.y + v3.y)) + ((v4.y + v5.y) + (v6.y + v7.y));
    }
    for (; j < end; j++) {
        int s = g_csrc[j];
        float2 v = T2[(size_t)s * 32 + lane];
        a.x += v.x;
        a.y += v.y;
    }
    float dv = g_dinv[warp];
    float2 bb = ((const float2*)b)[lane];
    float2 h;
    h.x = fmaxf(fmaf(a.x, dv, bb.x), 0.f);
    h.y = fmaxf(fmaf(a.y, dv, bb.y), 0.f);
    ((float2*)g_H)[(size_t)layer * n * 32 + (size_t)warp * 32 + lane] = h;
}

// ---------------- fused softmax + weighted sum + output GEMM ---------------------
__global__ void __launch_bounds__(128) k_final(const float* __restrict__ Wout,
                                               const float* __restrict__ bout,
                                               float* __restrict__ out, int n) {
    __shared__ float shW[64 * 40];
    __shared__ float shB[40];
    __shared__ float shS[16][64];
    int tid = threadIdx.x;
    for (int i = tid; i < 64 * 40; i += 128) shW[i] = Wout[i];
    if (tid < 40) shB[tid] = bout[tid];

    int nodeBase = blockIdx.x * 16;
    int nl = tid >> 3;
    int dg = tid & 7;
    int node = nodeBase + nl;
    if (node < n) {
        float s0 = g_scores[node];
        float s1 = g_scores[n + node];
        float s2 = g_scores[2 * n + node];
        float s3 = g_scores[3 * n + node];
        float m = fmaxf(fmaxf(s0, s1), fmaxf(s2, s3));
        float e0 = __expf(s0 - m), e1 = __expf(s1 - m);
        float e2 = __expf(s2 - m), e3 = __expf(s3 - m);
        float inv = 1.0f / (e0 + e1 + e2 + e3);
        e0 *= inv; e1 *= inv; e2 *= inv; e3 *= inv;
        size_t nh = (size_t)n * 64;
        size_t off0 = (size_t)node * 64 + dg * 8;
#pragma unroll
        for (int dd = 0; dd < 8; dd++) {
            size_t o = off0 + dd;
            float v = e0 * g_H[o] + e1 * g_H[nh + o] + e2 * g_H[2 * nh + o] + e3 * g_H[3 * nh + o];
            shS[nl][dg * 8 + dd] = v;
        }
    }
    __syncthreads();

    for (int o = tid; o < 16 * 40; o += 128) {
        int n2 = o / 40, c = o - n2 * 40;
        int node2 = nodeBase + n2;
        if (node2 < n) {
            float acc = shB[c];
#pragma unroll
            for (int k = 0; k < 64; k++) acc = fmaf(shS[n2][k], shW[k * 40 + c], acc);
            out[(size_t)node2 * 40 + c] = acc;
        }
    }
}

// ---------------- launch: 3-stream pipelined fork/join ---------------------------
extern "C" void kernel_launch(void* const* d_in, const int* in_sizes, int n_in,
                              void* d_out, int out_size) {
    const float* x    = (const float*)d_in[0];
    const int*   ei   = (const int*)d_in[1];   // int32 on device
    const float* W0   = (const float*)d_in[2];
    const float* b0   = (const float*)d_in[3];
    const float* Ws   = (const float*)d_in[4];
    const float* bs   = (const float*)d_in[5];
    const float* Wq   = (const float*)d_in[6];
    const float* Wk   = (const float*)d_in[7];
    const float* Wout = (const float*)d_in[8];
    const float* bout = (const float*)d_in[9];
    float* out        = (float*)d_out;

    int n = in_sizes[0] / 128;
    int E = in_sizes[1] / 2;
    int nparts = (n + SCAN_BLK - 1) / SCAN_BLK;

    // split node range into 2 halves (h0 rounded to 128 for gemm tiles)
    int nh0 = ((n / 2) + 127) / 128 * 128;
    if (nh0 > n) nh0 = n;
    int gB0 = (nh0 + 127) / 128;                  // gemm blocks half0
    int gB1 = (n - nh0 + 127) / 128;              // gemm blocks half1
    int gaB0 = (nh0 * 32 + 255) / 256;            // gather blocks half0
    int gaB1 = ((n - nh0) * 32 + 255) / 256;      // gather blocks half1
    int scoreBlocks = (n + 127) / 128;

    // lazily created host resources (not device memory)
    static cudaStream_t sB = nullptr, sC = nullptr;
    static cudaEvent_t evStart, evScan1, evFill;
    static cudaEvent_t eGm[4][2], eGa[4][2], eS[4];
    if (!sB) {
        cudaStreamCreateWithFlags(&sB, cudaStreamNonBlocking);
        cudaStreamCreateWithFlags(&sC, cudaStreamNonBlocking);
        cudaEventCreateWithFlags(&evStart, cudaEventDisableTiming);
        cudaEventCreateWithFlags(&evScan1, cudaEventDisableTiming);
        cudaEventCreateWithFlags(&evFill, cudaEventDisableTiming);
        for (int l = 0; l < 4; l++) {
            cudaEventCreateWithFlags(&eGm[l][0], cudaEventDisableTiming);
            cudaEventCreateWithFlags(&eGm[l][1], cudaEventDisableTiming);
            cudaEventCreateWithFlags(&eGa[l][0], cudaEventDisableTiming);
            cudaEventCreateWithFlags(&eGa[l][1], cudaEventDisableTiming);
            cudaEventCreateWithFlags(&eS[l], cudaEventDisableTiming);
        }
    }

    // ---- head on stream A (default): degree + dinv ----
    k_zerocnt<<<(n + 255) / 256, 256>>>(n);
    k_count<<<(E + 255) / 256, 256>>>(ei, E);
    k_scan1<<<nparts, 256>>>(n);
    cudaEventRecord(evScan1, 0);
    cudaEventRecord(evStart, 0);

    // ---- stream C (aux): k_M + CSR finish ----
    cudaStreamWaitEvent(sC, evStart, 0);
    k_M<<<4, 1024, 0, sC>>>(Wq, Wk);
    k_scan2<<<1, MAX_PARTS, 0, sC>>>(nparts, n);
    k_scan3<<<nparts, 256, 0, sC>>>(n);
    k_fill<<<(E + 255) / 256, 256, 0, sC>>>(ei, E);
    cudaEventRecord(evFill, sC);

    // ---- gemm0 split across A and B ----
    cudaStreamWaitEvent(sB, evScan1, 0);
    k_gemm<128><<<gB0, 256>>>(x, -1, W0, n, 0, nh0);                 // A
    cudaEventRecord(eGm[0][0], 0);
    k_gemm<128><<<gB1, 256, 0, sB>>>(x, -1, W0, n, nh0, n);          // B
    cudaEventRecord(eGm[0][1], sB);

    // ---- pipelined layer loop ----
    for (int l = 0; l < 4; l++) {
        const float* b = (l == 0) ? b0 : (bs + (size_t)(l - 1) * 64);

        // gather_l(h0) on A: needs gemm_l(h1) (h0 same-stream) (+ fill at l==0)
        cudaStreamWaitEvent(0, eGm[l][1], 0);
        if (l == 0) cudaStreamWaitEvent(0, evFill, 0);
        k_gather<<<gaB0, 256>>>(l, b, n, 0, nh0);
        cudaEventRecord(eGa[l][0], 0);

        // gather_l(h1) on B: needs gemm_l(h0)
        cudaStreamWaitEvent(sB, eGm[l][0], 0);
        if (l == 0) cudaStreamWaitEvent(sB, evFill, 0);
        k_gather<<<gaB1, 256, 0, sB>>>(l, b, n, nh0, n);
        cudaEventRecord(eGa[l][1], sB);

        // score_l on C: needs both gather halves
        cudaStreamWaitEvent(sC, eGa[l][0], 0);
        cudaStreamWaitEvent(sC, eGa[l][1], 0);
        k_score<<<scoreBlocks, 256, 0, sC>>>(l * n, (l + 1) * n);
        cudaEventRecord(eS[l], sC);

        // gemm_{l+1} per half, same stream as its gather half (implicit dep)
        if (l < 3) {
            const float* W = Ws + (size_t)l * 64 * 64;
            k_gemm<64><<<gB0, 256>>>(nullptr, l, W, n, 0, nh0);      // A
            cudaEventRecord(eGm[l + 1][0], 0);
            k_gemm<64><<<gB1, 256, 0, sB>>>(nullptr, l, W, n, nh0, n); // B
            cudaEventRecord(eGm[l + 1][1], sB);
        }
    }

    // ---- join: all scores + gather3(h1), then final on A ----
    for (int l = 0; l < 4; l++) cudaStreamWaitEvent(0, eS[l], 0);
    cudaStreamWaitEvent(0, eGa[3][1], 0);
    k_final<<<(n + 15) / 16, 128>>>(Wout, bout, out, n);
}